// round 1
// baseline (speedup 1.0000x reference)
#include <cuda_runtime.h>
#include <math.h>
#include <float.h>

// Problem constants (fixed by the reference)
#define BB 8
#define SS 1024
#define DD 512
#define HH 8
#define DH 64
#define MTOT (BB*SS)   // 8192 rows

// Scratch (allocation-free rule: __device__ globals)
__device__ float g_q [BB*SS*DD];
__device__ float g_k [BB*SS*DD];
__device__ float g_v [BB*SS*DD];
__device__ float g_ao[BB*SS*DD];

// ---------------------------------------------------------------------------
// GEMM: C[M,N] = A[M,K] @ W[K,N], fp32. BM=128, BN=64, BK=16, 256 threads,
// 8x4 per-thread tile. A staged transposed in smem for float4 reads.
// ---------------------------------------------------------------------------
__global__ __launch_bounds__(256) void gemm_kernel(
    const float* __restrict__ A, const float* __restrict__ W,
    float* __restrict__ C, int M, int N, int K)
{
    __shared__ float As[16][132];   // [k][m], pitch 132 keeps 16B alignment
    __shared__ float Bs[16][68];    // [k][n]

    const int tid = threadIdx.x;
    const int tx  = tid & 15;       // 16 col-groups of 4
    const int ty  = tid >> 4;       // 16 row-groups of 8
    const int bm  = blockIdx.x * 128;
    const int bn  = blockIdx.y * 64;

    float acc[8][4];
    #pragma unroll
    for (int i = 0; i < 8; i++)
        #pragma unroll
        for (int j = 0; j < 4; j++) acc[i][j] = 0.f;

    for (int k0 = 0; k0 < K; k0 += 16) {
        // Load A tile 128x16 (512 float4s, 2 per thread), store transposed
        #pragma unroll
        for (int p = 0; p < 2; p++) {
            int e  = tid + p * 256;
            int m  = e >> 2;             // 0..127
            int k4 = (e & 3) << 2;       // 0,4,8,12
            float4 a = *(const float4*)(A + (size_t)(bm + m) * K + k0 + k4);
            As[k4+0][m] = a.x; As[k4+1][m] = a.y;
            As[k4+2][m] = a.z; As[k4+3][m] = a.w;
        }
        // Load B tile 16x64 (256 float4s, 1 per thread), row-major
        {
            int kk = tid >> 4;           // 0..15
            int n4 = (tid & 15) << 2;    // 0..60
            *(float4*)&Bs[kk][n4] =
                *(const float4*)(W + (size_t)(k0 + kk) * N + bn + n4);
        }
        __syncthreads();

        #pragma unroll
        for (int kk = 0; kk < 16; kk++) {
            float4 a0 = *(float4*)&As[kk][ty * 8];
            float4 a1 = *(float4*)&As[kk][ty * 8 + 4];
            float4 b0 = *(float4*)&Bs[kk][tx * 4];
            float av[8] = {a0.x, a0.y, a0.z, a0.w, a1.x, a1.y, a1.z, a1.w};
            float bv[4] = {b0.x, b0.y, b0.z, b0.w};
            #pragma unroll
            for (int i = 0; i < 8; i++)
                #pragma unroll
                for (int j = 0; j < 4; j++)
                    acc[i][j] = fmaf(av[i], bv[j], acc[i][j]);
        }
        __syncthreads();
    }

    #pragma unroll
    for (int i = 0; i < 8; i++) {
        float4 o = make_float4(acc[i][0], acc[i][1], acc[i][2], acc[i][3]);
        *(float4*)(C + (size_t)(bm + ty * 8 + i) * N + bn + tx * 4) = o;
    }
}

// ---------------------------------------------------------------------------
// RoPE (+ optional 1/sqrt(Dh) scale). Layout (B,S,H,64); one thread per
// rotation pair (i, i+32). row = (b*S+s)*H + h  =>  s = (row>>3) & 1023.
// ---------------------------------------------------------------------------
__global__ void rope_kernel(float* __restrict__ x, float scale, int n)
{
    int idx = blockIdx.x * blockDim.x + threadIdx.x;
    if (idx >= n) return;
    int i   = idx & 31;
    int row = idx >> 5;
    int s   = (row >> 3) & (SS - 1);

    float inv_freq = powf(10000.0f, -(float)i * (1.0f / 32.0f));
    float ang = (float)s * inv_freq;
    float sn, cs;
    sincosf(ang, &sn, &cs);

    float* p = x + (size_t)row * 64;
    float x1 = p[i];
    float x2 = p[i + 32];
    p[i]      = (x1 * cs - x2 * sn) * scale;
    p[i + 32] = (x2 * cs + x1 * sn) * scale;
}

// ---------------------------------------------------------------------------
// Causal flash attention. One block = one (b,h) x 64-row Q tile.
// 256 threads, each owns a 4x4 micro-tile. Smem = exactly 48KB:
//   Qs[d][r], KPs[d][c] (K tile; later aliased as P[r][c]), Vs[c][d].
// ---------------------------------------------------------------------------
__global__ __launch_bounds__(256) void attn_kernel(
    const float* __restrict__ q, const float* __restrict__ k,
    const float* __restrict__ v, float* __restrict__ o)
{
    __shared__ float Qs [64][64];
    __shared__ float KPs[64][64];
    __shared__ float Vs [64][64];

    const int qt  = (int)gridDim.x - 1 - (int)blockIdx.x;  // big tiles first
    const int bh  = blockIdx.y;
    const int b   = bh >> 3, h = bh & 7;
    const int tid = threadIdx.x;
    const int r0  = (tid >> 4) << 2;   // q-row group
    const int c0  = (tid & 15) << 2;   // k-col / out-dim group

    // ---- load Q tile, transposed Qs[d][r] ----
    const float* qb = q + ((size_t)(b * SS + qt * 64)) * 512 + h * 64;
    #pragma unroll
    for (int p = 0; p < 4; p++) {
        int e  = tid + p * 256;         // 1024 float4s
        int r  = e >> 4;
        int d4 = (e & 15) << 2;
        float4 t = *(const float4*)(qb + (size_t)r * 512 + d4);
        Qs[d4+0][r] = t.x; Qs[d4+1][r] = t.y;
        Qs[d4+2][r] = t.z; Qs[d4+3][r] = t.w;
    }

    float m_r[4], l_r[4], acc[4][4];
    #pragma unroll
    for (int i = 0; i < 4; i++) {
        m_r[i] = -FLT_MAX; l_r[i] = 0.f;
        #pragma unroll
        for (int j = 0; j < 4; j++) acc[i][j] = 0.f;
    }
    __syncthreads();

    for (int kt = 0; kt <= qt; kt++) {
        const float* kb = k + ((size_t)(b * SS + kt * 64)) * 512 + h * 64;
        const float* vb = v + ((size_t)(b * SS + kt * 64)) * 512 + h * 64;
        #pragma unroll
        for (int p = 0; p < 4; p++) {
            int e  = tid + p * 256;
            int c  = e >> 4;
            int d4 = (e & 15) << 2;
            float4 tk = *(const float4*)(kb + (size_t)c * 512 + d4);
            KPs[d4+0][c] = tk.x; KPs[d4+1][c] = tk.y;
            KPs[d4+2][c] = tk.z; KPs[d4+3][c] = tk.w;
            float4 tv = *(const float4*)(vb + (size_t)c * 512 + d4);
            *(float4*)&Vs[c][d4] = tv;
        }
        __syncthreads();

        // ---- S = Q @ K^T (q pre-scaled by 1/8 in rope) ----
        float sc[4][4];
        #pragma unroll
        for (int i = 0; i < 4; i++)
            #pragma unroll
            for (int j = 0; j < 4; j++) sc[i][j] = 0.f;

        #pragma unroll
        for (int d = 0; d < 64; d++) {
            float4 qv = *(float4*)&Qs [d][r0];
            float4 kv = *(float4*)&KPs[d][c0];
            float qa[4] = {qv.x, qv.y, qv.z, qv.w};
            float ka[4] = {kv.x, kv.y, kv.z, kv.w};
            #pragma unroll
            for (int i = 0; i < 4; i++)
                #pragma unroll
                for (int j = 0; j < 4; j++)
                    sc[i][j] = fmaf(qa[i], ka[j], sc[i][j]);
        }

        if (kt == qt) {   // diagonal tile: causal mask
            #pragma unroll
            for (int i = 0; i < 4; i++)
                #pragma unroll
                for (int j = 0; j < 4; j++)
                    if (c0 + j > r0 + i) sc[i][j] = -1.0e30f;
        }

        // ---- online softmax (row reduction over 16 lanes via shfl) ----
        #pragma unroll
        for (int i = 0; i < 4; i++) {
            float tm = fmaxf(fmaxf(sc[i][0], sc[i][1]),
                             fmaxf(sc[i][2], sc[i][3]));
            #pragma unroll
            for (int off = 8; off >= 1; off >>= 1)
                tm = fmaxf(tm, __shfl_xor_sync(0xffffffffu, tm, off));
            float mn    = fmaxf(m_r[i], tm);
            float alpha = expf(m_r[i] - mn);
            float rs = 0.f;
            #pragma unroll
            for (int j = 0; j < 4; j++) {
                float pe = expf(sc[i][j] - mn);
                sc[i][j] = pe;
                rs += pe;
            }
            #pragma unroll
            for (int off = 8; off >= 1; off >>= 1)
                rs += __shfl_xor_sync(0xffffffffu, rs, off);
            l_r[i] = l_r[i] * alpha + rs;
            m_r[i] = mn;
            #pragma unroll
            for (int j = 0; j < 4; j++) acc[i][j] *= alpha;
        }

        __syncthreads();          // all K reads done; reuse KPs as P[r][c]
        #pragma unroll
        for (int i = 0; i < 4; i++)
            *(float4*)&KPs[r0 + i][c0] =
                make_float4(sc[i][0], sc[i][1], sc[i][2], sc[i][3]);
        __syncthreads();

        // ---- O += P @ V ----
        #pragma unroll
        for (int c = 0; c < 64; c++) {
            float4 vv = *(float4*)&Vs[c][c0];
            float va[4] = {vv.x, vv.y, vv.z, vv.w};
            #pragma unroll
            for (int i = 0; i < 4; i++) {
                float pr = KPs[r0 + i][c];   // broadcast within half-warp
                #pragma unroll
                for (int j = 0; j < 4; j++)
                    acc[i][j] = fmaf(pr, va[j], acc[i][j]);
            }
        }
        __syncthreads();          // before next tile overwrites KPs/Vs
    }

    float* ob = o + ((size_t)(b * SS + qt * 64)) * 512 + h * 64;
    #pragma unroll
    for (int i = 0; i < 4; i++) {
        float inv = 1.0f / l_r[i];
        float4 ov = make_float4(acc[i][0]*inv, acc[i][1]*inv,
                                acc[i][2]*inv, acc[i][3]*inv);
        *(float4*)(ob + (size_t)(r0 + i) * 512 + c0) = ov;
    }
}

// ---------------------------------------------------------------------------
// Launch. Input order (metadata): query, value, key_in, Wq, Wk, Wv, Wo.
// ---------------------------------------------------------------------------
extern "C" void kernel_launch(void* const* d_in, const int* in_sizes, int n_in,
                              void* d_out, int out_size)
{
    const float* query  = (const float*)d_in[0];
    const float* value  = (const float*)d_in[1];
    const float* key_in = (const float*)d_in[2];
    const float* Wq     = (const float*)d_in[3];
    const float* Wk     = (const float*)d_in[4];
    const float* Wv     = (const float*)d_in[5];
    const float* Wo     = (const float*)d_in[6];
    float* out = (float*)d_out;

    float *q, *k, *v, *ao;
    cudaGetSymbolAddress((void**)&q,  g_q);
    cudaGetSymbolAddress((void**)&k,  g_k);
    cudaGetSymbolAddress((void**)&v,  g_v);
    cudaGetSymbolAddress((void**)&ao, g_ao);

    dim3 ggrid(MTOT / 128, DD / 64);   // (64, 8)
    gemm_kernel<<<ggrid, 256>>>(query,  Wq, q, MTOT, DD, DD);
    gemm_kernel<<<ggrid, 256>>>(key_in, Wk, k, MTOT, DD, DD);
    gemm_kernel<<<ggrid, 256>>>(value,  Wv, v, MTOT, DD, DD);

    const int nrope = BB * SS * HH * 32;      // 2,097,152
    rope_kernel<<<nrope / 256, 256>>>(q, 0.125f, nrope);  // 1/sqrt(64)
    rope_kernel<<<nrope / 256, 256>>>(k, 1.0f,   nrope);

    dim3 agrid(SS / 64, BB * HH);      // (16, 64)
    attn_kernel<<<agrid, 256>>>(q, k, v, ao);

    gemm_kernel<<<ggrid, 256>>>(ao, Wo, out, MTOT, DD, DD);
}

// round 4
// speedup vs baseline: 1.2333x; 1.2333x over previous
#include <cuda_runtime.h>
#include <math.h>
#include <float.h>
#include <stdint.h>

// Problem constants (fixed by the reference)
#define BB 8
#define SS 1024
#define DD 512
#define HH 8
#define DH 64
#define MTOT (BB*SS)   // 8192 rows

// Scratch (allocation-free rule: __device__ globals)
__device__ float g_q [BB*SS*DD];
__device__ float g_k [BB*SS*DD];
__device__ float g_v [BB*SS*DD];
__device__ float g_ao[BB*SS*DD];

// ---------------------------------------------------------------------------
// TF32 helpers: 3xTF32 split (hi = rna(x), lo = rna(x - hi))
// ---------------------------------------------------------------------------
__device__ __forceinline__ void split_tf32(float x, uint32_t& hi, uint32_t& lo)
{
    uint32_t h;
    asm("cvt.rna.tf32.f32 %0, %1;" : "=r"(h) : "f"(x));
    float r = x - __uint_as_float(h);
    uint32_t l;
    asm("cvt.rna.tf32.f32 %0, %1;" : "=r"(l) : "f"(r));
    hi = h; lo = l;
}

__device__ __forceinline__ void mma_tf32(float* c, const uint32_t* a, const uint32_t* b)
{
    asm volatile(
        "mma.sync.aligned.m16n8k8.row.col.f32.tf32.tf32.f32 "
        "{%0,%1,%2,%3}, {%4,%5,%6,%7}, {%8,%9}, {%0,%1,%2,%3};\n"
        : "+f"(c[0]), "+f"(c[1]), "+f"(c[2]), "+f"(c[3])
        : "r"(a[0]), "r"(a[1]), "r"(a[2]), "r"(a[3]),
          "r"(b[0]), "r"(b[1]));
}

// ---------------------------------------------------------------------------
// GEMM: C[M,N] = A[M,K] @ W[K,N], fp32 via 3xTF32 mma. BM=BN=128, BK=32.
// 256 threads = 8 warps (2 x 4): warp tile 64(m) x 32(n) = 4x4 mma tiles.
// ---------------------------------------------------------------------------
#define APITCH 36
#define BPITCH 136
__global__ __launch_bounds__(256) void gemm_tc(
    const float* __restrict__ A, const float* __restrict__ W,
    float* __restrict__ C, int M, int N, int K)
{
    __shared__ float As[128 * APITCH];
    __shared__ float Bs[32  * BPITCH];

    const int tid  = threadIdx.x;
    const int lane = tid & 31;
    const int wid  = tid >> 5;
    const int gid  = lane >> 2;
    const int tig  = lane & 3;
    const int wm   = wid >> 2;           // 0..1 -> 64 rows each
    const int wn   = wid & 3;            // 0..3 -> 32 cols each
    const int bm   = blockIdx.x * 128;
    const int bn   = blockIdx.y * 128;

    float c[4][4][4];
    #pragma unroll
    for (int tm = 0; tm < 4; tm++)
        #pragma unroll
        for (int tn = 0; tn < 4; tn++)
            #pragma unroll
            for (int r = 0; r < 4; r++) c[tm][tn][r] = 0.f;

    for (int k0 = 0; k0 < K; k0 += 32) {
        // A tile 128x32 -> As[m][k], pitch 36 (float4 aligned: 144B)
        #pragma unroll
        for (int p = 0; p < 4; p++) {
            int e = tid + p * 256;
            int m = e >> 3, k4 = (e & 7) << 2;
            *(float4*)&As[m * APITCH + k4] =
                *(const float4*)(A + (size_t)(bm + m) * K + k0 + k4);
        }
        // B tile 32x128 -> Bs[k][n], pitch 136 (544B, 16B aligned)
        #pragma unroll
        for (int p = 0; p < 4; p++) {
            int e = tid + p * 256;
            int kk = e >> 5, n4 = (e & 31) << 2;
            *(float4*)&Bs[kk * BPITCH + n4] =
                *(const float4*)(W + (size_t)(k0 + kk) * N + bn + n4);
        }
        __syncthreads();

        #pragma unroll
        for (int ks = 0; ks < 4; ks++) {
            uint32_t ah[4][4], al[4][4], bh[4][2], bl[4][2];
            #pragma unroll
            for (int tm = 0; tm < 4; tm++) {
                int mr = wm * 64 + tm * 16 + gid;
                int kc = ks * 8 + tig;
                split_tf32(As[mr * APITCH + kc],           ah[tm][0], al[tm][0]);
                split_tf32(As[(mr + 8) * APITCH + kc],     ah[tm][1], al[tm][1]);
                split_tf32(As[mr * APITCH + kc + 4],       ah[tm][2], al[tm][2]);
                split_tf32(As[(mr + 8) * APITCH + kc + 4], ah[tm][3], al[tm][3]);
            }
            #pragma unroll
            for (int tn = 0; tn < 4; tn++) {
                int nc = wn * 32 + tn * 8 + gid;
                int kr = ks * 8 + tig;
                split_tf32(Bs[kr * BPITCH + nc],       bh[tn][0], bl[tn][0]);
                split_tf32(Bs[(kr + 4) * BPITCH + nc], bh[tn][1], bl[tn][1]);
            }
            #pragma unroll
            for (int tm = 0; tm < 4; tm++)
                #pragma unroll
                for (int tn = 0; tn < 4; tn++) {
                    mma_tf32(c[tm][tn], al[tm], bh[tn]);
                    mma_tf32(c[tm][tn], ah[tm], bl[tn]);
                    mma_tf32(c[tm][tn], ah[tm], bh[tn]);
                }
        }
        __syncthreads();
    }

    #pragma unroll
    for (int tm = 0; tm < 4; tm++)
        #pragma unroll
        for (int tn = 0; tn < 4; tn++) {
            int row = bm + wm * 64 + tm * 16 + gid;
            int col = bn + wn * 32 + tn * 8 + 2 * tig;
            *(float2*)(C + (size_t)row * N + col) =
                make_float2(c[tm][tn][0], c[tm][tn][1]);
            *(float2*)(C + (size_t)(row + 8) * N + col) =
                make_float2(c[tm][tn][2], c[tm][tn][3]);
        }
}

// ---------------------------------------------------------------------------
// RoPE (+ optional 1/sqrt(Dh) scale). Layout (B,S,H,64).
// ---------------------------------------------------------------------------
__global__ void rope_kernel(float* __restrict__ x, float scale, int n)
{
    int idx = blockIdx.x * blockDim.x + threadIdx.x;
    if (idx >= n) return;
    int i   = idx & 31;
    int row = idx >> 5;
    int s   = (row >> 3) & (SS - 1);

    float inv_freq = powf(10000.0f, -(float)i * (1.0f / 32.0f));
    float ang = (float)s * inv_freq;
    float sn, cs;
    sincosf(ang, &sn, &cs);

    float* p = x + (size_t)row * 64;
    float x1 = p[i];
    float x2 = p[i + 32];
    p[i]      = (x1 * cs - x2 * sn) * scale;
    p[i + 32] = (x2 * cs + x1 * sn) * scale;
}

// ---------------------------------------------------------------------------
// Causal flash attention, tensor-core version.
// Block = (qt, b*h): Br=128 q rows, Bc=32 key cols per inner tile.
// 256 threads = 8 warps; warp w owns q rows [w*16, w*16+16).
// Q lives in register fragments (hi/lo); P exchanged per-warp via smem.
// Per-warp early-out: tiles entirely above this warp's diagonal are skipped
// (P would be identically zero); warp still does cooperative loads + barriers.
// ---------------------------------------------------------------------------
#define KPITCH 68
#define VPITCH 72
#define PPITCH 36
__global__ __launch_bounds__(256) void attn_tc(
    const float* __restrict__ q, const float* __restrict__ k,
    const float* __restrict__ v, float* __restrict__ o)
{
    __shared__ float Ks[32 * KPITCH];
    __shared__ float Vs[32 * VPITCH];
    __shared__ float Ps[128 * PPITCH];

    const int qt   = (int)gridDim.x - 1 - (int)blockIdx.x;  // big tiles first
    const int bh   = blockIdx.y;
    const int b    = bh >> 3, h = bh & 7;
    const int tid  = threadIdx.x;
    const int lane = tid & 31;
    const int w    = tid >> 5;
    const int gid  = lane >> 2;
    const int tig  = lane & 3;
    const int rb   = w * 16;              // warp row base within 128

    // ---- Q register fragments (q pre-scaled by 1/8 in rope) ----
    uint32_t qh[8][4], ql[8][4];
    const float* qbase = q + ((size_t)(b * SS + qt * 128 + rb)) * 512 + h * 64;
    #pragma unroll
    for (int ks = 0; ks < 8; ks++) {
        int c0 = ks * 8 + tig;
        split_tf32(qbase[(size_t)gid * 512 + c0],           qh[ks][0], ql[ks][0]);
        split_tf32(qbase[(size_t)(gid + 8) * 512 + c0],     qh[ks][1], ql[ks][1]);
        split_tf32(qbase[(size_t)gid * 512 + c0 + 4],       qh[ks][2], ql[ks][2]);
        split_tf32(qbase[(size_t)(gid + 8) * 512 + c0 + 4], qh[ks][3], ql[ks][3]);
    }

    float m0 = -FLT_MAX, m1 = -FLT_MAX, l0 = 0.f, l1 = 0.f;
    float oacc[8][4];
    #pragma unroll
    for (int nt = 0; nt < 8; nt++)
        #pragma unroll
        for (int r = 0; r < 4; r++) oacc[nt][r] = 0.f;

    const int nkt = 4 * qt + 4;
    const int warp_max_row = qt * 128 + rb + 15;   // last q row this warp owns
    for (int kt = 0; kt < nkt; kt++) {
        const float* kb = k + ((size_t)(b * SS + kt * 32)) * 512 + h * 64;
        const float* vb = v + ((size_t)(b * SS + kt * 32)) * 512 + h * 64;
        #pragma unroll
        for (int p = 0; p < 2; p++) {
            int e = tid + p * 256;
            int cc = e >> 4, d4 = (e & 15) << 2;
            *(float4*)&Ks[cc * KPITCH + d4] =
                *(const float4*)(kb + (size_t)cc * 512 + d4);
            *(float4*)&Vs[cc * VPITCH + d4] =
                *(const float4*)(vb + (size_t)cc * 512 + d4);
        }
        __syncthreads();

        // Tile entirely above this warp's diagonal -> P == 0, skip compute.
        if (kt * 32 <= warp_max_row) {

        // ---- S = Q @ K^T (128x32, warp does 16x32 = 4 n-tiles) ----
        float s[4][4];
        #pragma unroll
        for (int nt = 0; nt < 4; nt++)
            #pragma unroll
            for (int r = 0; r < 4; r++) s[nt][r] = 0.f;

        #pragma unroll
        for (int ks = 0; ks < 8; ks++) {
            uint32_t kbh[4][2], kbl[4][2];
            #pragma unroll
            for (int nt = 0; nt < 4; nt++) {
                int cc = nt * 8 + gid;       // key index
                int dd = ks * 8 + tig;       // head dim
                split_tf32(Ks[cc * KPITCH + dd],     kbh[nt][0], kbl[nt][0]);
                split_tf32(Ks[cc * KPITCH + dd + 4], kbh[nt][1], kbl[nt][1]);
            }
            #pragma unroll
            for (int nt = 0; nt < 4; nt++) {
                mma_tf32(s[nt], ql[ks], kbh[nt]);
                mma_tf32(s[nt], qh[ks], kbl[nt]);
                mma_tf32(s[nt], qh[ks], kbh[nt]);
            }
        }

        // ---- causal mask (only when this warp's rows touch the diagonal) ----
        if (32 * kt + 31 > qt * 128 + rb) {
            int row0 = qt * 128 + rb + gid;
            #pragma unroll
            for (int nt = 0; nt < 4; nt++) {
                int colb = kt * 32 + nt * 8 + 2 * tig;
                if (colb     > row0)     s[nt][0] = -1.0e30f;
                if (colb + 1 > row0)     s[nt][1] = -1.0e30f;
                if (colb     > row0 + 8) s[nt][2] = -1.0e30f;
                if (colb + 1 > row0 + 8) s[nt][3] = -1.0e30f;
            }
        }

        // ---- online softmax (rows gid and gid+8; reduce over 4 tig lanes) ----
        {
            float mx0 = -FLT_MAX, mx1 = -FLT_MAX;
            #pragma unroll
            for (int nt = 0; nt < 4; nt++) {
                mx0 = fmaxf(mx0, fmaxf(s[nt][0], s[nt][1]));
                mx1 = fmaxf(mx1, fmaxf(s[nt][2], s[nt][3]));
            }
            mx0 = fmaxf(mx0, __shfl_xor_sync(0xffffffffu, mx0, 1));
            mx0 = fmaxf(mx0, __shfl_xor_sync(0xffffffffu, mx0, 2));
            mx1 = fmaxf(mx1, __shfl_xor_sync(0xffffffffu, mx1, 1));
            mx1 = fmaxf(mx1, __shfl_xor_sync(0xffffffffu, mx1, 2));

            float mn0 = fmaxf(m0, mx0), mn1 = fmaxf(m1, mx1);
            float a0 = __expf(m0 - mn0), a1 = __expf(m1 - mn1);
            float rs0 = 0.f, rs1 = 0.f;
            #pragma unroll
            for (int nt = 0; nt < 4; nt++) {
                s[nt][0] = __expf(s[nt][0] - mn0);
                s[nt][1] = __expf(s[nt][1] - mn0);
                s[nt][2] = __expf(s[nt][2] - mn1);
                s[nt][3] = __expf(s[nt][3] - mn1);
                rs0 += s[nt][0] + s[nt][1];
                rs1 += s[nt][2] + s[nt][3];
            }
            rs0 += __shfl_xor_sync(0xffffffffu, rs0, 1);
            rs0 += __shfl_xor_sync(0xffffffffu, rs0, 2);
            rs1 += __shfl_xor_sync(0xffffffffu, rs1, 1);
            rs1 += __shfl_xor_sync(0xffffffffu, rs1, 2);
            l0 = l0 * a0 + rs0;  l1 = l1 * a1 + rs1;
            m0 = mn0;            m1 = mn1;
            #pragma unroll
            for (int nt = 0; nt < 8; nt++) {
                oacc[nt][0] *= a0; oacc[nt][1] *= a0;
                oacc[nt][2] *= a1; oacc[nt][3] *= a1;
            }
        }

        // ---- P -> smem (warp-private region, warp-level sync suffices) ----
        #pragma unroll
        for (int nt = 0; nt < 4; nt++) {
            int colb = nt * 8 + 2 * tig;
            *(float2*)&Ps[(rb + gid) * PPITCH + colb] =
                make_float2(s[nt][0], s[nt][1]);
            *(float2*)&Ps[(rb + gid + 8) * PPITCH + colb] =
                make_float2(s[nt][2], s[nt][3]);
        }
        __syncwarp();

        // ---- O += P @ V (k-dim 32 = 4 k-steps; 8 n-tiles over dh=64) ----
        #pragma unroll
        for (int ks2 = 0; ks2 < 4; ks2++) {
            uint32_t pah[4], pal[4];
            int kc = ks2 * 8 + tig;
            split_tf32(Ps[(rb + gid) * PPITCH + kc],         pah[0], pal[0]);
            split_tf32(Ps[(rb + gid + 8) * PPITCH + kc],     pah[1], pal[1]);
            split_tf32(Ps[(rb + gid) * PPITCH + kc + 4],     pah[2], pal[2]);
            split_tf32(Ps[(rb + gid + 8) * PPITCH + kc + 4], pah[3], pal[3]);
            #pragma unroll
            for (int nt = 0; nt < 8; nt++) {
                int cr = ks2 * 8 + tig;
                int dc = nt * 8 + gid;
                uint32_t vbh[2], vbl[2];
                split_tf32(Vs[cr * VPITCH + dc],       vbh[0], vbl[0]);
                split_tf32(Vs[(cr + 4) * VPITCH + dc], vbh[1], vbl[1]);
                mma_tf32(oacc[nt], pal, vbh);
                mma_tf32(oacc[nt], pah, vbl);
                mma_tf32(oacc[nt], pah, vbh);
            }
        }
        __syncwarp();

        } // end per-warp skip

        __syncthreads();   // before next K/V overwrite
    }

    // ---- epilogue: divide by l, write out ----
    float inv0 = 1.0f / l0, inv1 = 1.0f / l1;
    float* ob = o + ((size_t)(b * SS + qt * 128 + rb)) * 512 + h * 64;
    #pragma unroll
    for (int nt = 0; nt < 8; nt++) {
        int col = nt * 8 + 2 * tig;
        *(float2*)(ob + (size_t)gid * 512 + col) =
            make_float2(oacc[nt][0] * inv0, oacc[nt][1] * inv0);
        *(float2*)(ob + (size_t)(gid + 8) * 512 + col) =
            make_float2(oacc[nt][2] * inv1, oacc[nt][3] * inv1);
    }
}

// ---------------------------------------------------------------------------
// Launch. Input order (metadata): query, value, key_in, Wq, Wk, Wv, Wo.
// ---------------------------------------------------------------------------
extern "C" void kernel_launch(void* const* d_in, const int* in_sizes, int n_in,
                              void* d_out, int out_size)
{
    const float* query  = (const float*)d_in[0];
    const float* value  = (const float*)d_in[1];
    const float* key_in = (const float*)d_in[2];
    const float* Wq     = (const float*)d_in[3];
    const float* Wk     = (const float*)d_in[4];
    const float* Wv     = (const float*)d_in[5];
    const float* Wo     = (const float*)d_in[6];
    float* out = (float*)d_out;

    float *q, *k, *v, *ao;
    cudaGetSymbolAddress((void**)&q,  g_q);
    cudaGetSymbolAddress((void**)&k,  g_k);
    cudaGetSymbolAddress((void**)&v,  g_v);
    cudaGetSymbolAddress((void**)&ao, g_ao);

    dim3 ggrid(MTOT / 128, DD / 128);   // (64, 4)
    gemm_tc<<<ggrid, 256>>>(query,  Wq, q, MTOT, DD, DD);
    gemm_tc<<<ggrid, 256>>>(key_in, Wk, k, MTOT, DD, DD);
    gemm_tc<<<ggrid, 256>>>(value,  Wv, v, MTOT, DD, DD);

    const int nrope = BB * SS * HH * 32;      // 2,097,152
    rope_kernel<<<nrope / 256, 256>>>(q, 0.125f, nrope);  // 1/sqrt(64)
    rope_kernel<<<nrope / 256, 256>>>(k, 1.0f,   nrope);

    dim3 agrid(SS / 128, BB * HH);      // (8, 64)
    attn_tc<<<agrid, 256>>>(q, k, v, ao);

    gemm_tc<<<ggrid, 256>>>(ao, Wo, out, MTOT, DD, DD);
}

// round 7
// speedup vs baseline: 1.9593x; 1.5887x over previous
#include <cuda_runtime.h>
#include <cuda_bf16.h>
#include <math.h>
#include <float.h>
#include <stdint.h>

// Problem constants
#define BB 8
#define SS 1024
#define DD 512
#define HH 8
#define MTOT (BB*SS)   // 8192
#define GK 512
#define GN 512

// Scratch (__device__ globals per allocation-free rule)
__device__ float g_q [BB*SS*DD];
__device__ float g_k [BB*SS*DD];
__device__ float g_v [BB*SS*DD];
__device__ float g_ao[BB*SS*DD];
__device__ __nv_bfloat16 g_ah[MTOT*GK], g_al[MTOT*GK];   // split activations
__device__ __nv_bfloat16 g_bh[GN*GK],  g_bl[GN*GK];      // split+transposed W

// ===========================================================================
// bf16 2-term split helpers
// ===========================================================================
__device__ __forceinline__ void split_bf16x2(float x0, float x1,
                                             uint32_t& hi, uint32_t& lo)
{
    __nv_bfloat16 h0 = __float2bfloat16(x0);
    __nv_bfloat16 h1 = __float2bfloat16(x1);
    __nv_bfloat16 l0 = __float2bfloat16(x0 - __bfloat162float(h0));
    __nv_bfloat16 l1 = __float2bfloat16(x1 - __bfloat162float(h1));
    __nv_bfloat162 H = __halves2bfloat162(h0, h1);
    __nv_bfloat162 L = __halves2bfloat162(l0, l1);
    hi = *(uint32_t*)&H;
    lo = *(uint32_t*)&L;
}

__device__ __forceinline__ void mma_bf16(float* c, const uint32_t* a, const uint32_t* b)
{
    asm volatile(
        "mma.sync.aligned.m16n8k16.row.col.f32.bf16.bf16.f32 "
        "{%0,%1,%2,%3}, {%4,%5,%6,%7}, {%8,%9}, {%0,%1,%2,%3};\n"
        : "+f"(c[0]), "+f"(c[1]), "+f"(c[2]), "+f"(c[3])
        : "r"(a[0]), "r"(a[1]), "r"(a[2]), "r"(a[3]),
          "r"(b[0]), "r"(b[1]));
}

// ===========================================================================
// Prep: split activation f32 -> bf16 hi/lo (element i -> hi[i], lo[i])
// ===========================================================================
__global__ void split_a_kernel(const float* __restrict__ x,
                               __nv_bfloat16* __restrict__ hi,
                               __nv_bfloat16* __restrict__ lo, int n4)
{
    int idx = blockIdx.x * blockDim.x + threadIdx.x;
    if (idx >= n4) return;
    float4 v = ((const float4*)x)[idx];
    uint32_t h01, l01, h23, l23;
    split_bf16x2(v.x, v.y, h01, l01);
    split_bf16x2(v.z, v.w, h23, l23);
    ((uint2*)hi)[idx] = make_uint2(h01, h23);
    ((uint2*)lo)[idx] = make_uint2(l01, l23);
}

// Prep: W [K,N] f32 -> transposed bf16 hi/lo [N,K]
__global__ void split_wt_kernel(const float* __restrict__ w,
                                __nv_bfloat16* __restrict__ hi,
                                __nv_bfloat16* __restrict__ lo)
{
    int idx = blockIdx.x * blockDim.x + threadIdx.x;   // 512*512
    int kk = idx & (GK - 1);
    int nn = idx >> 9;
    float x = w[(size_t)kk * GN + nn];
    __nv_bfloat16 h = __float2bfloat16(x);
    __nv_bfloat16 l = __float2bfloat16(x - __bfloat162float(h));
    hi[(size_t)nn * GK + kk] = h;
    lo[(size_t)nn * GK + kk] = l;
}

// ===========================================================================
// GEMM: C[M,N] = (Ah+Al) @ (Bh+Bl)^T, fp32 out, bf16 m16n8k16 2-term split.
// BM=BN=128, BK=32. 256 threads = 8 warps (2x4): warp tile 64(m) x 32(n).
// Smem tiles stored as uint32 k-pairs: [row][20 words] (32 bf16 + pad).
// Bank map: (20*row + w) mod 32 -> conflict-free for fragment loads.
// ===========================================================================
#define GP 20   // words per row (40 bf16)
__global__ __launch_bounds__(256) void gemm_bf16(
    const __nv_bfloat16* __restrict__ Ah, const __nv_bfloat16* __restrict__ Al,
    const __nv_bfloat16* __restrict__ Bh, const __nv_bfloat16* __restrict__ Bl,
    float* __restrict__ C)
{
    __shared__ uint32_t AsH[128 * GP], AsL[128 * GP];
    __shared__ uint32_t BsH[128 * GP], BsL[128 * GP];   // 4 x 10240B = 40KB

    const int tid  = threadIdx.x;
    const int lane = tid & 31;
    const int wid  = tid >> 5;
    const int gid  = lane >> 2;
    const int tig  = lane & 3;
    const int wm   = wid >> 2;           // 0..1 -> 64 rows each
    const int wn   = wid & 3;            // 0..3 -> 32 cols each
    const int bm   = blockIdx.x * 128;
    const int bn   = blockIdx.y * 128;

    float c[4][4][4];
    #pragma unroll
    for (int tm = 0; tm < 4; tm++)
        #pragma unroll
        for (int tn = 0; tn < 4; tn++)
            #pragma unroll
            for (int r = 0; r < 4; r++) c[tm][tn][r] = 0.f;

    for (int k0 = 0; k0 < GK; k0 += 32) {
        // Each tile: 128 rows x 32 bf16 = 512 uint4; 2 per thread per buffer.
        #pragma unroll
        for (int p = 0; p < 2; p++) {
            int e = tid + p * 256;
            int r = e >> 2, cc = e & 3;          // cc: which uint4 (8 bf16)
            size_t ga = (size_t)(bm + r) * GK + k0 + cc * 8;
            size_t gb = (size_t)(bn + r) * GK + k0 + cc * 8;
            *(uint4*)&AsH[r * GP + cc * 4] = *(const uint4*)(Ah + ga);
            *(uint4*)&AsL[r * GP + cc * 4] = *(const uint4*)(Al + ga);
            *(uint4*)&BsH[r * GP + cc * 4] = *(const uint4*)(Bh + gb);
            *(uint4*)&BsL[r * GP + cc * 4] = *(const uint4*)(Bl + gb);
        }
        __syncthreads();

        #pragma unroll
        for (int ks = 0; ks < 2; ks++) {         // two k16 steps per chunk
            uint32_t ah[4][4], al[4][4], bh[4][2], bl[4][2];
            #pragma unroll
            for (int tm = 0; tm < 4; tm++) {
                int mr = wm * 64 + tm * 16 + gid;
                int w0 = ks * 8 + tig;
                ah[tm][0] = AsH[mr * GP + w0];
                ah[tm][1] = AsH[(mr + 8) * GP + w0];
                ah[tm][2] = AsH[mr * GP + w0 + 4];
                ah[tm][3] = AsH[(mr + 8) * GP + w0 + 4];
                al[tm][0] = AsL[mr * GP + w0];
                al[tm][1] = AsL[(mr + 8) * GP + w0];
                al[tm][2] = AsL[mr * GP + w0 + 4];
                al[tm][3] = AsL[(mr + 8) * GP + w0 + 4];
            }
            #pragma unroll
            for (int tn = 0; tn < 4; tn++) {
                int nc = wn * 32 + tn * 8 + gid;
                int w0 = ks * 8 + tig;
                bh[tn][0] = BsH[nc * GP + w0];
                bh[tn][1] = BsH[nc * GP + w0 + 4];
                bl[tn][0] = BsL[nc * GP + w0];
                bl[tn][1] = BsL[nc * GP + w0 + 4];
            }
            #pragma unroll
            for (int tm = 0; tm < 4; tm++)
                #pragma unroll
                for (int tn = 0; tn < 4; tn++) {
                    mma_bf16(c[tm][tn], al[tm], bh[tn]);
                    mma_bf16(c[tm][tn], ah[tm], bl[tn]);
                    mma_bf16(c[tm][tn], ah[tm], bh[tn]);
                }
        }
        __syncthreads();
    }

    #pragma unroll
    for (int tm = 0; tm < 4; tm++)
        #pragma unroll
        for (int tn = 0; tn < 4; tn++) {
            int row = bm + wm * 64 + tm * 16 + gid;
            int col = bn + wn * 32 + tn * 8 + 2 * tig;
            *(float2*)(C + (size_t)row * GN + col) =
                make_float2(c[tm][tn][0], c[tm][tn][1]);
            *(float2*)(C + (size_t)(row + 8) * GN + col) =
                make_float2(c[tm][tn][2], c[tm][tn][3]);
        }
}

// ===========================================================================
// RoPE (+ optional 1/8 scale). Layout (B,S,H,64).
// ===========================================================================
__global__ void rope_kernel(float* __restrict__ x, float scale, int n)
{
    int idx = blockIdx.x * blockDim.x + threadIdx.x;
    if (idx >= n) return;
    int i   = idx & 31;
    int row = idx >> 5;
    int s   = (row >> 3) & (SS - 1);
    float inv_freq = powf(10000.0f, -(float)i * (1.0f / 32.0f));
    float ang = (float)s * inv_freq;
    float sn, cs;
    sincosf(ang, &sn, &cs);
    float* p = x + (size_t)row * 64;
    float x1 = p[i], x2 = p[i + 32];
    p[i]      = (x1 * cs - x2 * sn) * scale;
    p[i + 32] = (x2 * cs + x1 * sn) * scale;
}

// ===========================================================================
// Causal flash attention, bf16 m16n8k16 2-term split.
// Block = (qt, b*h): Br=128 q rows, Bc=32 key cols per inner tile.
// 256 threads = 8 warps; warp w owns q rows [w*16, w*16+16).
// ===========================================================================
#define KPITCH 68
#define VPITCH 72
#define PPITCH 36
__global__ __launch_bounds__(256) void attn_tc(
    const float* __restrict__ q, const float* __restrict__ k,
    const float* __restrict__ v, float* __restrict__ o)
{
    __shared__ float Ks[32 * KPITCH];
    __shared__ float Vs[32 * VPITCH];
    __shared__ float Ps[128 * PPITCH];

    const int qt   = (int)gridDim.x - 1 - (int)blockIdx.x;
    const int bh   = blockIdx.y;
    const int b    = bh >> 3, h = bh & 7;
    const int tid  = threadIdx.x;
    const int lane = tid & 31;
    const int w    = tid >> 5;
    const int gid  = lane >> 2;
    const int tig  = lane & 3;
    const int rb   = w * 16;

    // Q fragments (hi/lo bf16x2), rows gid / gid+8; 4 k16-chunks over dh=64
    uint32_t qh[4][4], ql[4][4];
    const float* qbase = q + ((size_t)(b * SS + qt * 128 + rb)) * 512 + h * 64;
    #pragma unroll
    for (int kc = 0; kc < 4; kc++) {
        int c0 = kc * 16 + 2 * tig;
        float2 v0 = *(const float2*)(qbase + (size_t)gid * 512 + c0);
        float2 v1 = *(const float2*)(qbase + (size_t)(gid + 8) * 512 + c0);
        float2 v2 = *(const float2*)(qbase + (size_t)gid * 512 + c0 + 8);
        float2 v3 = *(const float2*)(qbase + (size_t)(gid + 8) * 512 + c0 + 8);
        split_bf16x2(v0.x, v0.y, qh[kc][0], ql[kc][0]);
        split_bf16x2(v1.x, v1.y, qh[kc][1], ql[kc][1]);
        split_bf16x2(v2.x, v2.y, qh[kc][2], ql[kc][2]);
        split_bf16x2(v3.x, v3.y, qh[kc][3], ql[kc][3]);
    }

    float m0 = -FLT_MAX, m1 = -FLT_MAX, l0 = 0.f, l1 = 0.f;
    float oacc[8][4];
    #pragma unroll
    for (int nt = 0; nt < 8; nt++)
        #pragma unroll
        for (int r = 0; r < 4; r++) oacc[nt][r] = 0.f;

    const int nkt = 4 * qt + 4;
    const int warp_max_row = qt * 128 + rb + 15;
    for (int kt = 0; kt < nkt; kt++) {
        const float* kb = k + ((size_t)(b * SS + kt * 32)) * 512 + h * 64;
        const float* vb = v + ((size_t)(b * SS + kt * 32)) * 512 + h * 64;
        #pragma unroll
        for (int p = 0; p < 2; p++) {
            int e = tid + p * 256;
            int cc = e >> 4, d4 = (e & 15) << 2;
            *(float4*)&Ks[cc * KPITCH + d4] =
                *(const float4*)(kb + (size_t)cc * 512 + d4);
            *(float4*)&Vs[cc * VPITCH + d4] =
                *(const float4*)(vb + (size_t)cc * 512 + d4);
        }
        __syncthreads();

        if (kt * 32 <= warp_max_row) {   // per-warp causal early-out

        // ---- S = Q @ K^T ----
        float s[4][4];
        #pragma unroll
        for (int nt = 0; nt < 4; nt++)
            #pragma unroll
            for (int r = 0; r < 4; r++) s[nt][r] = 0.f;

        #pragma unroll
        for (int kc = 0; kc < 4; kc++) {
            uint32_t kbh[4][2], kbl[4][2];
            #pragma unroll
            for (int nt = 0; nt < 4; nt++) {
                int cc = nt * 8 + gid;
                int dd = kc * 16 + 2 * tig;
                float2 kv0 = *(const float2*)&Ks[cc * KPITCH + dd];
                float2 kv1 = *(const float2*)&Ks[cc * KPITCH + dd + 8];
                split_bf16x2(kv0.x, kv0.y, kbh[nt][0], kbl[nt][0]);
                split_bf16x2(kv1.x, kv1.y, kbh[nt][1], kbl[nt][1]);
            }
            #pragma unroll
            for (int nt = 0; nt < 4; nt++) {
                mma_bf16(s[nt], ql[kc], kbh[nt]);
                mma_bf16(s[nt], qh[kc], kbl[nt]);
                mma_bf16(s[nt], qh[kc], kbh[nt]);
            }
        }

        // ---- causal mask ----
        if (32 * kt + 31 > qt * 128 + rb) {
            int row0 = qt * 128 + rb + gid;
            #pragma unroll
            for (int nt = 0; nt < 4; nt++) {
                int colb = kt * 32 + nt * 8 + 2 * tig;
                if (colb     > row0)     s[nt][0] = -1.0e30f;
                if (colb + 1 > row0)     s[nt][1] = -1.0e30f;
                if (colb     > row0 + 8) s[nt][2] = -1.0e30f;
                if (colb + 1 > row0 + 8) s[nt][3] = -1.0e30f;
            }
        }

        // ---- online softmax ----
        {
            float mx0 = -FLT_MAX, mx1 = -FLT_MAX;
            #pragma unroll
            for (int nt = 0; nt < 4; nt++) {
                mx0 = fmaxf(mx0, fmaxf(s[nt][0], s[nt][1]));
                mx1 = fmaxf(mx1, fmaxf(s[nt][2], s[nt][3]));
            }
            mx0 = fmaxf(mx0, __shfl_xor_sync(0xffffffffu, mx0, 1));
            mx0 = fmaxf(mx0, __shfl_xor_sync(0xffffffffu, mx0, 2));
            mx1 = fmaxf(mx1, __shfl_xor_sync(0xffffffffu, mx1, 1));
            mx1 = fmaxf(mx1, __shfl_xor_sync(0xffffffffu, mx1, 2));

            float mn0 = fmaxf(m0, mx0), mn1 = fmaxf(m1, mx1);
            float a0 = __expf(m0 - mn0), a1 = __expf(m1 - mn1);
            float rs0 = 0.f, rs1 = 0.f;
            #pragma unroll
            for (int nt = 0; nt < 4; nt++) {
                s[nt][0] = __expf(s[nt][0] - mn0);
                s[nt][1] = __expf(s[nt][1] - mn0);
                s[nt][2] = __expf(s[nt][2] - mn1);
                s[nt][3] = __expf(s[nt][3] - mn1);
                rs0 += s[nt][0] + s[nt][1];
                rs1 += s[nt][2] + s[nt][3];
            }
            rs0 += __shfl_xor_sync(0xffffffffu, rs0, 1);
            rs0 += __shfl_xor_sync(0xffffffffu, rs0, 2);
            rs1 += __shfl_xor_sync(0xffffffffu, rs1, 1);
            rs1 += __shfl_xor_sync(0xffffffffu, rs1, 2);
            l0 = l0 * a0 + rs0;  l1 = l1 * a1 + rs1;
            m0 = mn0;            m1 = mn1;
            #pragma unroll
            for (int nt = 0; nt < 8; nt++) {
                oacc[nt][0] *= a0; oacc[nt][1] *= a0;
                oacc[nt][2] *= a1; oacc[nt][3] *= a1;
            }
        }

        // ---- P -> smem (warp-private rows) ----
        #pragma unroll
        for (int nt = 0; nt < 4; nt++) {
            int colb = nt * 8 + 2 * tig;
            *(float2*)&Ps[(rb + gid) * PPITCH + colb] =
                make_float2(s[nt][0], s[nt][1]);
            *(float2*)&Ps[(rb + gid + 8) * PPITCH + colb] =
                make_float2(s[nt][2], s[nt][3]);
        }
        __syncwarp();

        // ---- O += P @ V (2 k16-chunks over 32 keys, 8 n-tiles over dh) ----
        #pragma unroll
        for (int ks2 = 0; ks2 < 2; ks2++) {
            int kc = ks2 * 16 + 2 * tig;
            uint32_t pah[4], pal[4];
            float2 p0 = *(const float2*)&Ps[(rb + gid) * PPITCH + kc];
            float2 p1 = *(const float2*)&Ps[(rb + gid + 8) * PPITCH + kc];
            float2 p2 = *(const float2*)&Ps[(rb + gid) * PPITCH + kc + 8];
            float2 p3 = *(const float2*)&Ps[(rb + gid + 8) * PPITCH + kc + 8];
            split_bf16x2(p0.x, p0.y, pah[0], pal[0]);
            split_bf16x2(p1.x, p1.y, pah[1], pal[1]);
            split_bf16x2(p2.x, p2.y, pah[2], pal[2]);
            split_bf16x2(p3.x, p3.y, pah[3], pal[3]);
            #pragma unroll
            for (int nt = 0; nt < 8; nt++) {
                int dc = nt * 8 + gid;
                int r0 = ks2 * 16 + 2 * tig;
                uint32_t vbh[2], vbl[2];
                split_bf16x2(Vs[r0 * VPITCH + dc],       Vs[(r0 + 1) * VPITCH + dc],
                             vbh[0], vbl[0]);
                split_bf16x2(Vs[(r0 + 8) * VPITCH + dc], Vs[(r0 + 9) * VPITCH + dc],
                             vbh[1], vbl[1]);
                mma_bf16(oacc[nt], pal, vbh);
                mma_bf16(oacc[nt], pah, vbl);
                mma_bf16(oacc[nt], pah, vbh);
            }
        }
        __syncwarp();

        } // per-warp skip

        __syncthreads();
    }

    float inv0 = 1.0f / l0, inv1 = 1.0f / l1;
    float* ob = o + ((size_t)(b * SS + qt * 128 + rb)) * 512 + h * 64;
    #pragma unroll
    for (int nt = 0; nt < 8; nt++) {
        int col = nt * 8 + 2 * tig;
        *(float2*)(ob + (size_t)gid * 512 + col) =
            make_float2(oacc[nt][0] * inv0, oacc[nt][1] * inv0);
        *(float2*)(ob + (size_t)(gid + 8) * 512 + col) =
            make_float2(oacc[nt][2] * inv1, oacc[nt][3] * inv1);
    }
}

// ===========================================================================
// Launch. Input order: query, value, key_in, Wq, Wk, Wv, Wo.
// ===========================================================================
extern "C" void kernel_launch(void* const* d_in, const int* in_sizes, int n_in,
                              void* d_out, int out_size)
{
    const float* query  = (const float*)d_in[0];
    const float* value  = (const float*)d_in[1];
    const float* key_in = (const float*)d_in[2];
    const float* Wq     = (const float*)d_in[3];
    const float* Wk     = (const float*)d_in[4];
    const float* Wv     = (const float*)d_in[5];
    const float* Wo     = (const float*)d_in[6];
    float* out = (float*)d_out;

    float *q, *k, *v, *ao;
    __nv_bfloat16 *ah, *al, *bh, *bl;
    cudaGetSymbolAddress((void**)&q,  g_q);
    cudaGetSymbolAddress((void**)&k,  g_k);
    cudaGetSymbolAddress((void**)&v,  g_v);
    cudaGetSymbolAddress((void**)&ao, g_ao);
    cudaGetSymbolAddress((void**)&ah, g_ah);
    cudaGetSymbolAddress((void**)&al, g_al);
    cudaGetSymbolAddress((void**)&bh, g_bh);
    cudaGetSymbolAddress((void**)&bl, g_bl);

    const int nA4 = MTOT * GK / 4;          // float4 count for activations
    dim3 ggrid(MTOT / 128, GN / 128);       // (64, 4)

    // Q = query @ Wq
    split_wt_kernel<<<GN * GK / 256, 256>>>(Wq, bh, bl);
    split_a_kernel<<<(nA4 + 255) / 256, 256>>>(query, ah, al, nA4);
    gemm_bf16<<<ggrid, 256>>>(ah, al, bh, bl, q);
    // K = key_in @ Wk
    split_wt_kernel<<<GN * GK / 256, 256>>>(Wk, bh, bl);
    split_a_kernel<<<(nA4 + 255) / 256, 256>>>(key_in, ah, al, nA4);
    gemm_bf16<<<ggrid, 256>>>(ah, al, bh, bl, k);
    // V = value @ Wv
    split_wt_kernel<<<GN * GK / 256, 256>>>(Wv, bh, bl);
    split_a_kernel<<<(nA4 + 255) / 256, 256>>>(value, ah, al, nA4);
    gemm_bf16<<<ggrid, 256>>>(ah, al, bh, bl, v);

    const int nrope = BB * SS * HH * 32;
    rope_kernel<<<nrope / 256, 256>>>(q, 0.125f, nrope);
    rope_kernel<<<nrope / 256, 256>>>(k, 1.0f, nrope);

    dim3 agrid(SS / 128, BB * HH);          // (8, 64)
    attn_tc<<<agrid, 256>>>(q, k, v, ao);

    // out = ao @ Wo
    split_wt_kernel<<<GN * GK / 256, 256>>>(Wo, bh, bl);
    split_a_kernel<<<(nA4 + 255) / 256, 256>>>(ao, ah, al, nA4);
    gemm_bf16<<<ggrid, 256>>>(ah, al, bh, bl, out);
}

// round 9
// speedup vs baseline: 1.9774x; 1.0092x over previous
#include <cuda_runtime.h>
#include <cuda_bf16.h>
#include <math.h>
#include <float.h>
#include <stdint.h>

// Problem constants
#define BB 8
#define SS 1024
#define DD 512
#define HH 8
#define MTOT (BB*SS)   // 8192
#define GK 512
#define GN 512

// Scratch (__device__ globals per allocation-free rule)
__device__ float g_q [BB*SS*DD];
__device__ float g_k [BB*SS*DD];
__device__ float g_v [BB*SS*DD];
__device__ float g_ao[BB*SS*DD];
__device__ __nv_bfloat16 g_ah[MTOT*GK], g_al[MTOT*GK];   // split activations
__device__ __nv_bfloat16 g_bh[GN*GK],  g_bl[GN*GK];      // split+transposed W
// attention operands, pre-split:
__device__ __nv_bfloat16 g_qh2[BB*HH*SS*64], g_ql2[BB*HH*SS*64];  // (b,h,s,d)
__device__ __nv_bfloat16 g_kh2[BB*HH*SS*64], g_kl2[BB*HH*SS*64];  // (b,h,s,d)
__device__ __nv_bfloat16 g_vh2[BB*HH*64*SS], g_vl2[BB*HH*64*SS];  // (b,h,d,s)

// ===========================================================================
// bf16 2-term split helpers
// ===========================================================================
__device__ __forceinline__ void split_bf16x2(float x0, float x1,
                                             uint32_t& hi, uint32_t& lo)
{
    __nv_bfloat16 h0 = __float2bfloat16(x0);
    __nv_bfloat16 h1 = __float2bfloat16(x1);
    __nv_bfloat16 l0 = __float2bfloat16(x0 - __bfloat162float(h0));
    __nv_bfloat16 l1 = __float2bfloat16(x1 - __bfloat162float(h1));
    __nv_bfloat162 H = __halves2bfloat162(h0, h1);
    __nv_bfloat162 L = __halves2bfloat162(l0, l1);
    hi = *(uint32_t*)&H;
    lo = *(uint32_t*)&L;
}

__device__ __forceinline__ void mma_bf16(float* c, const uint32_t* a, const uint32_t* b)
{
    asm volatile(
        "mma.sync.aligned.m16n8k16.row.col.f32.bf16.bf16.f32 "
        "{%0,%1,%2,%3}, {%4,%5,%6,%7}, {%8,%9}, {%0,%1,%2,%3};\n"
        : "+f"(c[0]), "+f"(c[1]), "+f"(c[2]), "+f"(c[3])
        : "r"(a[0]), "r"(a[1]), "r"(a[2]), "r"(a[3]),
          "r"(b[0]), "r"(b[1]));
}

// ===========================================================================
// Prep kernels
// ===========================================================================
__global__ void split_a_kernel(const float* __restrict__ x,
                               __nv_bfloat16* __restrict__ hi,
                               __nv_bfloat16* __restrict__ lo, int n4)
{
    int idx = blockIdx.x * blockDim.x + threadIdx.x;
    if (idx >= n4) return;
    float4 v = ((const float4*)x)[idx];
    uint32_t h01, l01, h23, l23;
    split_bf16x2(v.x, v.y, h01, l01);
    split_bf16x2(v.z, v.w, h23, l23);
    ((uint2*)hi)[idx] = make_uint2(h01, h23);
    ((uint2*)lo)[idx] = make_uint2(l01, l23);
}

__global__ void split_wt_kernel(const float* __restrict__ w,
                                __nv_bfloat16* __restrict__ hi,
                                __nv_bfloat16* __restrict__ lo)
{
    int idx = blockIdx.x * blockDim.x + threadIdx.x;   // 512*512
    int kk = idx & (GK - 1);
    int nn = idx >> 9;
    float x = w[(size_t)kk * GN + nn];
    __nv_bfloat16 h = __float2bfloat16(x);
    __nv_bfloat16 l = __float2bfloat16(x - __bfloat162float(h));
    hi[(size_t)nn * GK + kk] = h;
    lo[(size_t)nn * GK + kk] = l;
}

// RoPE + scale + bf16-split; (b,s,h,d) f32 -> (b,h,s,d) bf16 hi/lo.
__global__ void rope_split_kernel(const float* __restrict__ x,
                                  __nv_bfloat16* __restrict__ xh,
                                  __nv_bfloat16* __restrict__ xl,
                                  float scale, int n)
{
    int idx = blockIdx.x * blockDim.x + threadIdx.x;
    if (idx >= n) return;
    int i   = idx & 31;
    int row = idx >> 5;                 // (b*S+s)*H + h
    int s   = (row >> 3) & (SS - 1);
    int h   = row & 7;
    int b   = row >> 13;

    float inv_freq = powf(10000.0f, -(float)i * (1.0f / 32.0f));
    float ang = (float)s * inv_freq;
    float sn, cs;
    sincosf(ang, &sn, &cs);

    const float* p = x + (size_t)row * 64;
    float x1 = p[i], x2 = p[i + 32];
    float r1 = (x1 * cs - x2 * sn) * scale;
    float r2 = (x2 * cs + x1 * sn) * scale;

    size_t orow = ((size_t)((b * HH + h) * SS + s)) * 64;
    __nv_bfloat16 h1 = __float2bfloat16(r1);
    __nv_bfloat16 h2 = __float2bfloat16(r2);
    xh[orow + i]      = h1;
    xh[orow + i + 32] = h2;
    xl[orow + i]      = __float2bfloat16(r1 - __bfloat162float(h1));
    xl[orow + i + 32] = __float2bfloat16(r2 - __bfloat162float(h2));
}

// V transpose-split: (b,s,h,d) f32 -> (b,h,d,s) bf16 hi/lo. 32x32 smem tiles.
__global__ void v_split_kernel(const float* __restrict__ v,
                               __nv_bfloat16* __restrict__ vh,
                               __nv_bfloat16* __restrict__ vl)
{
    __shared__ float tile[32][33];
    const int bh = blockIdx.z;
    const int b = bh >> 3, h = bh & 7;
    const int s0 = blockIdx.x * 32, d0 = blockIdx.y * 32;
    const int tx = threadIdx.x, ty = threadIdx.y;   // (32, 8)

    #pragma unroll
    for (int j = 0; j < 4; j++) {
        int s = s0 + ty + j * 8;
        tile[ty + j * 8][tx] =
            v[((size_t)(b * SS + s) * HH + h) * 64 + d0 + tx];
    }
    __syncthreads();
    #pragma unroll
    for (int j = 0; j < 4; j++) {
        int d = d0 + ty + j * 8;
        float x = tile[tx][ty + j * 8];
        __nv_bfloat16 hi = __float2bfloat16(x);
        size_t oi = ((size_t)((b * HH + h) * 64 + d)) * SS + s0 + tx;
        vh[oi] = hi;
        vl[oi] = __float2bfloat16(x - __bfloat162float(hi));
    }
}

// ===========================================================================
// GEMM: C[M,N] = (Ah+Al) @ (Bh+Bl)^T, bf16 m16n8k16 2-term split.
// BM=BN=128, BK=32. 256 threads = 8 warps (2x4). Register prefetch pipeline.
// ===========================================================================
#define GP 20   // words per row
__global__ __launch_bounds__(256) void gemm_bf16(
    const __nv_bfloat16* __restrict__ Ah, const __nv_bfloat16* __restrict__ Al,
    const __nv_bfloat16* __restrict__ Bh, const __nv_bfloat16* __restrict__ Bl,
    float* __restrict__ C)
{
    __shared__ uint32_t AsH[128 * GP], AsL[128 * GP];
    __shared__ uint32_t BsH[128 * GP], BsL[128 * GP];

    const int tid  = threadIdx.x;
    const int lane = tid & 31;
    const int wid  = tid >> 5;
    const int gid  = lane >> 2;
    const int tig  = lane & 3;
    const int wm   = wid >> 2;
    const int wn   = wid & 3;
    const int bm   = blockIdx.x * 128;
    const int bn   = blockIdx.y * 128;

    float c[4][4][4];
    #pragma unroll
    for (int tm = 0; tm < 4; tm++)
        #pragma unroll
        for (int tn = 0; tn < 4; tn++)
            #pragma unroll
            for (int r = 0; r < 4; r++) c[tm][tn][r] = 0.f;

    // load chunk 0
    #pragma unroll
    for (int p = 0; p < 2; p++) {
        int e = tid + p * 256;
        int r = e >> 2, cc = e & 3;
        size_t ga = (size_t)(bm + r) * GK + cc * 8;
        size_t gb = (size_t)(bn + r) * GK + cc * 8;
        *(uint4*)&AsH[r * GP + cc * 4] = *(const uint4*)(Ah + ga);
        *(uint4*)&AsL[r * GP + cc * 4] = *(const uint4*)(Al + ga);
        *(uint4*)&BsH[r * GP + cc * 4] = *(const uint4*)(Bh + gb);
        *(uint4*)&BsL[r * GP + cc * 4] = *(const uint4*)(Bl + gb);
    }
    __syncthreads();

    uint4 pAh[2], pAl[2], pBh[2], pBl[2];
    for (int it = 0; it < 16; it++) {
        if (it < 15) {                        // prefetch next chunk to regs
            int k0n = (it + 1) * 32;
            #pragma unroll
            for (int p = 0; p < 2; p++) {
                int e = tid + p * 256;
                int r = e >> 2, cc = e & 3;
                size_t ga = (size_t)(bm + r) * GK + k0n + cc * 8;
                size_t gb = (size_t)(bn + r) * GK + k0n + cc * 8;
                pAh[p] = *(const uint4*)(Ah + ga);
                pAl[p] = *(const uint4*)(Al + ga);
                pBh[p] = *(const uint4*)(Bh + gb);
                pBl[p] = *(const uint4*)(Bl + gb);
            }
        }

        #pragma unroll
        for (int ks = 0; ks < 2; ks++) {
            uint32_t ah[4][4], al[4][4], bh[4][2], bl[4][2];
            #pragma unroll
            for (int tm = 0; tm < 4; tm++) {
                int mr = wm * 64 + tm * 16 + gid;
                int w0 = ks * 8 + tig;
                ah[tm][0] = AsH[mr * GP + w0];
                ah[tm][1] = AsH[(mr + 8) * GP + w0];
                ah[tm][2] = AsH[mr * GP + w0 + 4];
                ah[tm][3] = AsH[(mr + 8) * GP + w0 + 4];
                al[tm][0] = AsL[mr * GP + w0];
                al[tm][1] = AsL[(mr + 8) * GP + w0];
                al[tm][2] = AsL[mr * GP + w0 + 4];
                al[tm][3] = AsL[(mr + 8) * GP + w0 + 4];
            }
            #pragma unroll
            for (int tn = 0; tn < 4; tn++) {
                int nc = wn * 32 + tn * 8 + gid;
                int w0 = ks * 8 + tig;
                bh[tn][0] = BsH[nc * GP + w0];
                bh[tn][1] = BsH[nc * GP + w0 + 4];
                bl[tn][0] = BsL[nc * GP + w0];
                bl[tn][1] = BsL[nc * GP + w0 + 4];
            }
            #pragma unroll
            for (int tm = 0; tm < 4; tm++)
                #pragma unroll
                for (int tn = 0; tn < 4; tn++) {
                    mma_bf16(c[tm][tn], al[tm], bh[tn]);
                    mma_bf16(c[tm][tn], ah[tm], bl[tn]);
                    mma_bf16(c[tm][tn], ah[tm], bh[tn]);
                }
        }
        __syncthreads();

        if (it < 15) {
            #pragma unroll
            for (int p = 0; p < 2; p++) {
                int e = tid + p * 256;
                int r = e >> 2, cc = e & 3;
                *(uint4*)&AsH[r * GP + cc * 4] = pAh[p];
                *(uint4*)&AsL[r * GP + cc * 4] = pAl[p];
                *(uint4*)&BsH[r * GP + cc * 4] = pBh[p];
                *(uint4*)&BsL[r * GP + cc * 4] = pBl[p];
            }
            __syncthreads();
        }
    }

    #pragma unroll
    for (int tm = 0; tm < 4; tm++)
        #pragma unroll
        for (int tn = 0; tn < 4; tn++) {
            int row = bm + wm * 64 + tm * 16 + gid;
            int col = bn + wn * 32 + tn * 8 + 2 * tig;
            *(float2*)(C + (size_t)row * GN + col) =
                make_float2(c[tm][tn][0], c[tm][tn][1]);
            *(float2*)(C + (size_t)(row + 8) * GN + col) =
                make_float2(c[tm][tn][2], c[tm][tn][3]);
        }
}

// ===========================================================================
// Causal flash attention, bf16 m16n8k16, pre-split operands,
// S->P register reuse (no P smem).
// Block = (qt, b*h): Br=128 q rows, Bc=32 keys/tile. 8 warps x 16 rows.
// Smem: KsH/KsL [32 c][36 words] (d-pairs), VsH/VsL [64 d][20 words] (c-pairs).
// ===========================================================================
#define KP2 36
#define VP2 20
__global__ __launch_bounds__(256) void attn_tc(
    const __nv_bfloat16* __restrict__ qh2, const __nv_bfloat16* __restrict__ ql2,
    const __nv_bfloat16* __restrict__ kh2, const __nv_bfloat16* __restrict__ kl2,
    const __nv_bfloat16* __restrict__ vh2, const __nv_bfloat16* __restrict__ vl2,
    float* __restrict__ o)
{
    __shared__ uint32_t KsH[32 * KP2], KsL[32 * KP2];
    __shared__ uint32_t VsH[64 * VP2], VsL[64 * VP2];

    const int qt   = (int)gridDim.x - 1 - (int)blockIdx.x;
    const int bh   = blockIdx.y;
    const int b    = bh >> 3, h = bh & 7;
    const int tid  = threadIdx.x;
    const int lane = tid & 31;
    const int w    = tid >> 5;
    const int gid  = lane >> 2;
    const int tig  = lane & 3;
    const int rb   = w * 16;

    // ---- Q fragments straight from pre-split gmem ----
    uint32_t qfh[4][4], qfl[4][4];
    {
        const size_t qrow0 = ((size_t)((b * HH + h) * SS + qt * 128 + rb)) * 64;
        #pragma unroll
        for (int kc = 0; kc < 4; kc++) {
            int c0 = kc * 16 + 2 * tig;
            qfh[kc][0] = *(const uint32_t*)(qh2 + qrow0 + (size_t)gid * 64 + c0);
            qfh[kc][1] = *(const uint32_t*)(qh2 + qrow0 + (size_t)(gid + 8) * 64 + c0);
            qfh[kc][2] = *(const uint32_t*)(qh2 + qrow0 + (size_t)gid * 64 + c0 + 8);
            qfh[kc][3] = *(const uint32_t*)(qh2 + qrow0 + (size_t)(gid + 8) * 64 + c0 + 8);
            qfl[kc][0] = *(const uint32_t*)(ql2 + qrow0 + (size_t)gid * 64 + c0);
            qfl[kc][1] = *(const uint32_t*)(ql2 + qrow0 + (size_t)(gid + 8) * 64 + c0);
            qfl[kc][2] = *(const uint32_t*)(ql2 + qrow0 + (size_t)gid * 64 + c0 + 8);
            qfl[kc][3] = *(const uint32_t*)(ql2 + qrow0 + (size_t)(gid + 8) * 64 + c0 + 8);
        }
    }

    float m0 = -FLT_MAX, m1 = -FLT_MAX, l0 = 0.f, l1 = 0.f;
    float oacc[8][4];
    #pragma unroll
    for (int nt = 0; nt < 8; nt++)
        #pragma unroll
        for (int r = 0; r < 4; r++) oacc[nt][r] = 0.f;

    const int nkt = 4 * qt + 4;
    const int warp_max_row = qt * 128 + rb + 15;
    for (int kt = 0; kt < nkt; kt++) {
        // ---- tile loads: K rows 32x(64 bf16), V rows 64x(32 bf16) ----
        {
            const __nv_bfloat16* khb = kh2 + ((size_t)((b * HH + h) * SS + kt * 32)) * 64;
            const __nv_bfloat16* klb = kl2 + ((size_t)((b * HH + h) * SS + kt * 32)) * 64;
            int cc = tid >> 3, q4 = tid & 7;
            *(uint4*)&KsH[cc * KP2 + q4 * 4] = *(const uint4*)(khb + (size_t)cc * 64 + q4 * 8);
            *(uint4*)&KsL[cc * KP2 + q4 * 4] = *(const uint4*)(klb + (size_t)cc * 64 + q4 * 8);

            int d = tid >> 2, v4 = tid & 3;
            const __nv_bfloat16* vhb = vh2 + ((size_t)((b * HH + h) * 64 + d)) * SS + kt * 32;
            const __nv_bfloat16* vlb = vl2 + ((size_t)((b * HH + h) * 64 + d)) * SS + kt * 32;
            *(uint4*)&VsH[d * VP2 + v4 * 4] = *(const uint4*)(vhb + v4 * 8);
            *(uint4*)&VsL[d * VP2 + v4 * 4] = *(const uint4*)(vlb + v4 * 8);
        }
        __syncthreads();

        if (kt * 32 <= warp_max_row) {   // per-warp causal early-out

        // ---- S = Q @ K^T ----
        float s[4][4];
        #pragma unroll
        for (int nt = 0; nt < 4; nt++)
            #pragma unroll
            for (int r = 0; r < 4; r++) s[nt][r] = 0.f;

        #pragma unroll
        for (int kc = 0; kc < 4; kc++) {
            uint32_t kbh[4][2], kbl[4][2];
            #pragma unroll
            for (int nt = 0; nt < 4; nt++) {
                int cc = nt * 8 + gid;
                int w0 = kc * 8 + tig;
                kbh[nt][0] = KsH[cc * KP2 + w0];
                kbh[nt][1] = KsH[cc * KP2 + w0 + 4];
                kbl[nt][0] = KsL[cc * KP2 + w0];
                kbl[nt][1] = KsL[cc * KP2 + w0 + 4];
            }
            #pragma unroll
            for (int nt = 0; nt < 4; nt++) {
                mma_bf16(s[nt], qfl[kc], kbh[nt]);
                mma_bf16(s[nt], qfh[kc], kbl[nt]);
                mma_bf16(s[nt], qfh[kc], kbh[nt]);
            }
        }

        // ---- causal mask ----
        if (32 * kt + 31 > qt * 128 + rb) {
            int row0 = qt * 128 + rb + gid;
            #pragma unroll
            for (int nt = 0; nt < 4; nt++) {
                int colb = kt * 32 + nt * 8 + 2 * tig;
                if (colb     > row0)     s[nt][0] = -1.0e30f;
                if (colb + 1 > row0)     s[nt][1] = -1.0e30f;
                if (colb     > row0 + 8) s[nt][2] = -1.0e30f;
                if (colb + 1 > row0 + 8) s[nt][3] = -1.0e30f;
            }
        }

        // ---- online softmax ----
        {
            float mx0 = -FLT_MAX, mx1 = -FLT_MAX;
            #pragma unroll
            for (int nt = 0; nt < 4; nt++) {
                mx0 = fmaxf(mx0, fmaxf(s[nt][0], s[nt][1]));
                mx1 = fmaxf(mx1, fmaxf(s[nt][2], s[nt][3]));
            }
            mx0 = fmaxf(mx0, __shfl_xor_sync(0xffffffffu, mx0, 1));
            mx0 = fmaxf(mx0, __shfl_xor_sync(0xffffffffu, mx0, 2));
            mx1 = fmaxf(mx1, __shfl_xor_sync(0xffffffffu, mx1, 1));
            mx1 = fmaxf(mx1, __shfl_xor_sync(0xffffffffu, mx1, 2));

            float mn0 = fmaxf(m0, mx0), mn1 = fmaxf(m1, mx1);
            float a0 = __expf(m0 - mn0), a1 = __expf(m1 - mn1);
            float rs0 = 0.f, rs1 = 0.f;
            #pragma unroll
            for (int nt = 0; nt < 4; nt++) {
                s[nt][0] = __expf(s[nt][0] - mn0);
                s[nt][1] = __expf(s[nt][1] - mn0);
                s[nt][2] = __expf(s[nt][2] - mn1);
                s[nt][3] = __expf(s[nt][3] - mn1);
                rs0 += s[nt][0] + s[nt][1];
                rs1 += s[nt][2] + s[nt][3];
            }
            rs0 += __shfl_xor_sync(0xffffffffu, rs0, 1);
            rs0 += __shfl_xor_sync(0xffffffffu, rs0, 2);
            rs1 += __shfl_xor_sync(0xffffffffu, rs1, 1);
            rs1 += __shfl_xor_sync(0xffffffffu, rs1, 2);
            l0 = l0 * a0 + rs0;  l1 = l1 * a1 + rs1;
            m0 = mn0;            m1 = mn1;
            #pragma unroll
            for (int nt = 0; nt < 8; nt++) {
                oacc[nt][0] *= a0; oacc[nt][1] *= a0;
                oacc[nt][2] *= a1; oacc[nt][3] *= a1;
            }
        }

        // ---- O += P @ V : S fragments ARE the PV A fragments ----
        #pragma unroll
        for (int ks2 = 0; ks2 < 2; ks2++) {
            uint32_t pah[4], pal[4];
            split_bf16x2(s[2*ks2][0],   s[2*ks2][1],   pah[0], pal[0]);
            split_bf16x2(s[2*ks2][2],   s[2*ks2][3],   pah[1], pal[1]);
            split_bf16x2(s[2*ks2+1][0], s[2*ks2+1][1], pah[2], pal[2]);
            split_bf16x2(s[2*ks2+1][2], s[2*ks2+1][3], pah[3], pal[3]);
            #pragma unroll
            for (int nt = 0; nt < 8; nt++) {
                int dn = nt * 8 + gid;
                int w0 = ks2 * 8 + tig;
                uint32_t vbh[2], vbl[2];
                vbh[0] = VsH[dn * VP2 + w0];
                vbh[1] = VsH[dn * VP2 + w0 + 4];
                vbl[0] = VsL[dn * VP2 + w0];
                vbl[1] = VsL[dn * VP2 + w0 + 4];
                mma_bf16(oacc[nt], pal, vbh);
                mma_bf16(oacc[nt], pah, vbl);
                mma_bf16(oacc[nt], pah, vbh);
            }
        }

        } // per-warp skip

        __syncthreads();
    }

    float inv0 = 1.0f / l0, inv1 = 1.0f / l1;
    float* ob = o + ((size_t)(b * SS + qt * 128 + rb)) * 512 + h * 64;
    #pragma unroll
    for (int nt = 0; nt < 8; nt++) {
        int col = nt * 8 + 2 * tig;
        *(float2*)(ob + (size_t)gid * 512 + col) =
            make_float2(oacc[nt][0] * inv0, oacc[nt][1] * inv0);
        *(float2*)(ob + (size_t)(gid + 8) * 512 + col) =
            make_float2(oacc[nt][2] * inv1, oacc[nt][3] * inv1);
    }
}

// ===========================================================================
// Launch. Input order: query, value, key_in, Wq, Wk, Wv, Wo.
// ===========================================================================
extern "C" void kernel_launch(void* const* d_in, const int* in_sizes, int n_in,
                              void* d_out, int out_size)
{
    const float* query  = (const float*)d_in[0];
    const float* value  = (const float*)d_in[1];
    const float* key_in = (const float*)d_in[2];
    const float* Wq     = (const float*)d_in[3];
    const float* Wk     = (const float*)d_in[4];
    const float* Wv     = (const float*)d_in[5];
    const float* Wo     = (const float*)d_in[6];
    float* out = (float*)d_out;

    float *q, *k, *v, *ao;
    __nv_bfloat16 *ah, *al, *bh, *bl;
    __nv_bfloat16 *qh2, *ql2, *kh2, *kl2, *vh2, *vl2;
    cudaGetSymbolAddress((void**)&q,  g_q);
    cudaGetSymbolAddress((void**)&k,  g_k);
    cudaGetSymbolAddress((void**)&v,  g_v);
    cudaGetSymbolAddress((void**)&ao, g_ao);
    cudaGetSymbolAddress((void**)&ah, g_ah);
    cudaGetSymbolAddress((void**)&al, g_al);
    cudaGetSymbolAddress((void**)&bh, g_bh);
    cudaGetSymbolAddress((void**)&bl, g_bl);
    cudaGetSymbolAddress((void**)&qh2, g_qh2);
    cudaGetSymbolAddress((void**)&ql2, g_ql2);
    cudaGetSymbolAddress((void**)&kh2, g_kh2);
    cudaGetSymbolAddress((void**)&kl2, g_kl2);
    cudaGetSymbolAddress((void**)&vh2, g_vh2);
    cudaGetSymbolAddress((void**)&vl2, g_vl2);

    const int nA4 = MTOT * GK / 4;
    dim3 ggrid(MTOT / 128, GN / 128);       // (64, 4)

    // Q = query @ Wq ; K = key_in @ Wk ; V = value @ Wv
    split_wt_kernel<<<GN * GK / 256, 256>>>(Wq, bh, bl);
    split_a_kernel<<<(nA4 + 255) / 256, 256>>>(query, ah, al, nA4);
    gemm_bf16<<<ggrid, 256>>>(ah, al, bh, bl, q);
    split_wt_kernel<<<GN * GK / 256, 256>>>(Wk, bh, bl);
    split_a_kernel<<<(nA4 + 255) / 256, 256>>>(key_in, ah, al, nA4);
    gemm_bf16<<<ggrid, 256>>>(ah, al, bh, bl, k);
    split_wt_kernel<<<GN * GK / 256, 256>>>(Wv, bh, bl);
    split_a_kernel<<<(nA4 + 255) / 256, 256>>>(value, ah, al, nA4);
    gemm_bf16<<<ggrid, 256>>>(ah, al, bh, bl, v);

    // rope + split q/k ; transpose-split v
    const int nrope = BB * SS * HH * 32;
    rope_split_kernel<<<nrope / 256, 256>>>(q, qh2, ql2, 0.125f, nrope);
    rope_split_kernel<<<nrope / 256, 256>>>(k, kh2, kl2, 1.0f, nrope);
    {
        dim3 vgrid(SS / 32, 2, BB * HH);
        dim3 vblk(32, 8);
        v_split_kernel<<<vgrid, vblk>>>(v, vh2, vl2);
    }

    dim3 agrid(SS / 128, BB * HH);          // (8, 64)
    attn_tc<<<agrid, 256>>>(qh2, ql2, kh2, kl2, vh2, vl2, ao);

    // out = ao @ Wo
    split_wt_kernel<<<GN * GK / 256, 256>>>(Wo, bh, bl);
    split_a_kernel<<<(nA4 + 255) / 256, 256>>>(ao, ah, al, nA4);
    gemm_bf16<<<ggrid, 256>>>(ah, al, bh, bl, out);
}

// round 12
// speedup vs baseline: 2.8508x; 1.4417x over previous
#include <cuda_runtime.h>
#include <cuda_fp16.h>
#include <math.h>
#include <float.h>
#include <stdint.h>

// Problem constants
#define BB 8
#define SS 1024
#define DD 512
#define HH 8
#define MTOT (BB*SS)   // 8192
#define GK 512
#define GN 512

// Scratch (__device__ globals per allocation-free rule)
__device__ float g_q [BB*SS*DD];
__device__ float g_k [BB*SS*DD];
__device__ float g_v [BB*SS*DD];
__device__ float g_ao[BB*SS*DD];
__device__ __half g_ah[MTOT*GK], g_al[MTOT*GK];      // split activations (hi/lo)
__device__ __half g_bh[GN*GK];                        // single-fp16 transposed W
// attention operands:
__device__ __half g_qh2[BB*HH*SS*64], g_ql2[BB*HH*SS*64];  // Q hi/lo (b,h,s,d)
__device__ __half g_kh2[BB*HH*SS*64];                      // K single (b,h,s,d)
__device__ __half g_vh2[BB*HH*64*SS];                      // V single (b,h,d,s)

// ===========================================================================
// fp16 helpers. 2-pass scheme: split ONE operand hi/lo (exact), quantize the
// other to single fp16. Error per stage = a*(b - fp16(b)) ~ 2^-11.
// ===========================================================================
__device__ __forceinline__ void split_f16x2(float x0, float x1,
                                            uint32_t& hi, uint32_t& lo)
{
    __half h0 = __float2half_rn(x0);
    __half h1 = __float2half_rn(x1);
    __half l0 = __float2half_rn(x0 - __half2float(h0));
    __half l1 = __float2half_rn(x1 - __half2float(h1));
    __half2 H = __halves2half2(h0, h1);
    __half2 L = __halves2half2(l0, l1);
    hi = *(uint32_t*)&H;
    lo = *(uint32_t*)&L;
}
__device__ __forceinline__ uint32_t pack_f16x2(float x0, float x1)
{
    __half2 H = __halves2half2(__float2half_rn(x0), __float2half_rn(x1));
    return *(uint32_t*)&H;
}

__device__ __forceinline__ void mma_f16(float* c, const uint32_t* a, const uint32_t* b)
{
    asm volatile(
        "mma.sync.aligned.m16n8k16.row.col.f32.f16.f16.f32 "
        "{%0,%1,%2,%3}, {%4,%5,%6,%7}, {%8,%9}, {%0,%1,%2,%3};\n"
        : "+f"(c[0]), "+f"(c[1]), "+f"(c[2]), "+f"(c[3])
        : "r"(a[0]), "r"(a[1]), "r"(a[2]), "r"(a[3]),
          "r"(b[0]), "r"(b[1]));
}

// ===========================================================================
// Prep kernels
// ===========================================================================
// Activations f32 -> fp16 hi/lo.
__global__ void split_a_kernel(const float* __restrict__ x,
                               __half* __restrict__ hi,
                               __half* __restrict__ lo, int n4)
{
    int idx = blockIdx.x * blockDim.x + threadIdx.x;
    if (idx >= n4) return;
    float4 v = ((const float4*)x)[idx];
    uint32_t h01, l01, h23, l23;
    split_f16x2(v.x, v.y, h01, l01);
    split_f16x2(v.z, v.w, h23, l23);
    ((uint2*)hi)[idx] = make_uint2(h01, h23);
    ((uint2*)lo)[idx] = make_uint2(l01, l23);
}

// W [K,N] f32 -> single fp16 transposed [N,K]; coalesced via 32x32 smem tiles.
__global__ void wt_conv_kernel(const float* __restrict__ w,
                               __half* __restrict__ hi)
{
    __shared__ float tile[32][33];
    const int k0 = blockIdx.x * 32, n0 = blockIdx.y * 32;
    const int tx = threadIdx.x, ty = threadIdx.y;   // (32, 8)
    #pragma unroll
    for (int j = 0; j < 4; j++)
        tile[ty + j * 8][tx] = w[(size_t)(k0 + ty + j * 8) * GN + n0 + tx];
    __syncthreads();
    #pragma unroll
    for (int j = 0; j < 4; j++) {
        int nn = n0 + ty + j * 8;
        int kk = k0 + tx;
        hi[(size_t)nn * GK + kk] = __float2half_rn(tile[tx][ty + j * 8]);
    }
}

// RoPE + scale + fp16 hi/lo split; (b,s,h,d) f32 -> (b,h,s,d).  (for Q)
__global__ void rope_split_kernel(const float* __restrict__ x,
                                  __half* __restrict__ xh,
                                  __half* __restrict__ xl,
                                  float scale, int n)
{
    int idx = blockIdx.x * blockDim.x + threadIdx.x;
    if (idx >= n) return;
    int i   = idx & 31;
    int row = idx >> 5;                 // (b*S+s)*H + h
    int s   = (row >> 3) & (SS - 1);
    int h   = row & 7;
    int b   = row >> 13;

    float inv_freq = powf(10000.0f, -(float)i * (1.0f / 32.0f));
    float ang = (float)s * inv_freq;
    float sn, cs;
    sincosf(ang, &sn, &cs);

    const float* p = x + (size_t)row * 64;
    float x1 = p[i], x2 = p[i + 32];
    float r1 = (x1 * cs - x2 * sn) * scale;
    float r2 = (x2 * cs + x1 * sn) * scale;

    size_t orow = ((size_t)((b * HH + h) * SS + s)) * 64;
    __half h1 = __float2half_rn(r1);
    __half h2 = __float2half_rn(r2);
    xh[orow + i]      = h1;
    xh[orow + i + 32] = h2;
    xl[orow + i]      = __float2half_rn(r1 - __half2float(h1));
    xl[orow + i + 32] = __float2half_rn(r2 - __half2float(h2));
}

// RoPE + single fp16; (b,s,h,d) f32 -> (b,h,s,d).  (for K)
__global__ void rope_conv_kernel(const float* __restrict__ x,
                                 __half* __restrict__ xh, int n)
{
    int idx = blockIdx.x * blockDim.x + threadIdx.x;
    if (idx >= n) return;
    int i   = idx & 31;
    int row = idx >> 5;
    int s   = (row >> 3) & (SS - 1);
    int h   = row & 7;
    int b   = row >> 13;

    float inv_freq = powf(10000.0f, -(float)i * (1.0f / 32.0f));
    float ang = (float)s * inv_freq;
    float sn, cs;
    sincosf(ang, &sn, &cs);

    const float* p = x + (size_t)row * 64;
    float x1 = p[i], x2 = p[i + 32];
    size_t orow = ((size_t)((b * HH + h) * SS + s)) * 64;
    xh[orow + i]      = __float2half_rn(x1 * cs - x2 * sn);
    xh[orow + i + 32] = __float2half_rn(x2 * cs + x1 * sn);
}

// V transpose + single fp16: (b,s,h,d) f32 -> (b,h,d,s). 32x32 smem tiles.
__global__ void v_conv_kernel(const float* __restrict__ v,
                              __half* __restrict__ vh)
{
    __shared__ float tile[32][33];
    const int bh = blockIdx.z;
    const int b = bh >> 3, h = bh & 7;
    const int s0 = blockIdx.x * 32, d0 = blockIdx.y * 32;
    const int tx = threadIdx.x, ty = threadIdx.y;   // (32, 8)

    #pragma unroll
    for (int j = 0; j < 4; j++) {
        int s = s0 + ty + j * 8;
        tile[ty + j * 8][tx] =
            v[((size_t)(b * SS + s) * HH + h) * 64 + d0 + tx];
    }
    __syncthreads();
    #pragma unroll
    for (int j = 0; j < 4; j++) {
        int d = d0 + ty + j * 8;
        size_t oi = ((size_t)((b * HH + h) * 64 + d)) * SS + s0 + tx;
        vh[oi] = __float2half_rn(tile[tx][ty + j * 8]);
    }
}

// ===========================================================================
// GEMM: C[M,N] = (Ah+Al) @ B16^T, fp16 m16n8k16 2-pass.
// BM=BN=128, BK=32. 256 threads = 8 warps (2x4): warp tile 64(m) x 32(n).
// Smem rows: [row][20 words] (32 fp16 + pad), conflict-free fragment loads.
// ===========================================================================
#define GP 20
__global__ __launch_bounds__(256) void gemm_f16(
    const __half* __restrict__ Ah, const __half* __restrict__ Al,
    const __half* __restrict__ Bh, float* __restrict__ C)
{
    __shared__ uint32_t AsH[128 * GP], AsL[128 * GP], Bs[128 * GP];

    const int tid  = threadIdx.x;
    const int lane = tid & 31;
    const int wid  = tid >> 5;
    const int gid  = lane >> 2;
    const int tig  = lane & 3;
    const int wm   = wid >> 2;
    const int wn   = wid & 3;
    const int bm   = blockIdx.x * 128;
    const int bn   = blockIdx.y * 128;

    float c[4][4][4];
    #pragma unroll
    for (int tm = 0; tm < 4; tm++)
        #pragma unroll
        for (int tn = 0; tn < 4; tn++)
            #pragma unroll
            for (int r = 0; r < 4; r++) c[tm][tn][r] = 0.f;

    for (int k0 = 0; k0 < GK; k0 += 32) {
        // 3 tiles x 512 uint4; 2 per thread per tile.
        #pragma unroll
        for (int p = 0; p < 2; p++) {
            int e = tid + p * 256;
            int r = e >> 2, cc = e & 3;
            size_t ga = (size_t)(bm + r) * GK + k0 + cc * 8;
            size_t gb = (size_t)(bn + r) * GK + k0 + cc * 8;
            *(uint4*)&AsH[r * GP + cc * 4] = *(const uint4*)(Ah + ga);
            *(uint4*)&AsL[r * GP + cc * 4] = *(const uint4*)(Al + ga);
            *(uint4*)&Bs [r * GP + cc * 4] = *(const uint4*)(Bh + gb);
        }
        __syncthreads();

        #pragma unroll
        for (int ks = 0; ks < 2; ks++) {
            uint32_t ah[4][4], al[4][4], bf[4][2];
            #pragma unroll
            for (int tm = 0; tm < 4; tm++) {
                int mr = wm * 64 + tm * 16 + gid;
                int w0 = ks * 8 + tig;
                ah[tm][0] = AsH[mr * GP + w0];
                ah[tm][1] = AsH[(mr + 8) * GP + w0];
                ah[tm][2] = AsH[mr * GP + w0 + 4];
                ah[tm][3] = AsH[(mr + 8) * GP + w0 + 4];
                al[tm][0] = AsL[mr * GP + w0];
                al[tm][1] = AsL[(mr + 8) * GP + w0];
                al[tm][2] = AsL[mr * GP + w0 + 4];
                al[tm][3] = AsL[(mr + 8) * GP + w0 + 4];
            }
            #pragma unroll
            for (int tn = 0; tn < 4; tn++) {
                int nc = wn * 32 + tn * 8 + gid;
                int w0 = ks * 8 + tig;
                bf[tn][0] = Bs[nc * GP + w0];
                bf[tn][1] = Bs[nc * GP + w0 + 4];
            }
            #pragma unroll
            for (int tm = 0; tm < 4; tm++)
                #pragma unroll
                for (int tn = 0; tn < 4; tn++) {
                    mma_f16(c[tm][tn], al[tm], bf[tn]);
                    mma_f16(c[tm][tn], ah[tm], bf[tn]);
                }
        }
        __syncthreads();
    }

    #pragma unroll
    for (int tm = 0; tm < 4; tm++)
        #pragma unroll
        for (int tn = 0; tn < 4; tn++) {
            int row = bm + wm * 64 + tm * 16 + gid;
            int col = bn + wn * 32 + tn * 8 + 2 * tig;
            *(float2*)(C + (size_t)row * GN + col) =
                make_float2(c[tm][tn][0], c[tm][tn][1]);
            *(float2*)(C + (size_t)(row + 8) * GN + col) =
                make_float2(c[tm][tn][2], c[tm][tn][3]);
        }
}

// ===========================================================================
// Causal flash attention, fp16 m16n8k16 2-pass.
// Q split hi/lo (exact), K single fp16; P split hi/lo (exact), V single fp16.
// Block = (qt, b*h): Br=128 q rows, Bc=32 keys/tile. 8 warps x 16 rows.
// ===========================================================================
#define KP2 36
#define VP2 20
__global__ __launch_bounds__(256) void attn_tc(
    const __half* __restrict__ qh2, const __half* __restrict__ ql2,
    const __half* __restrict__ kh2, const __half* __restrict__ vh2,
    float* __restrict__ o)
{
    __shared__ uint32_t KsH[32 * KP2];
    __shared__ uint32_t VsH[64 * VP2];

    const int qt   = (int)gridDim.x - 1 - (int)blockIdx.x;
    const int bh   = blockIdx.y;
    const int b    = bh >> 3, h = bh & 7;
    const int tid  = threadIdx.x;
    const int lane = tid & 31;
    const int w    = tid >> 5;
    const int gid  = lane >> 2;
    const int tig  = lane & 3;
    const int rb   = w * 16;

    uint32_t qfh[4][4], qfl[4][4];
    {
        const size_t qrow0 = ((size_t)((b * HH + h) * SS + qt * 128 + rb)) * 64;
        #pragma unroll
        for (int kc = 0; kc < 4; kc++) {
            int c0 = kc * 16 + 2 * tig;
            qfh[kc][0] = *(const uint32_t*)(qh2 + qrow0 + (size_t)gid * 64 + c0);
            qfh[kc][1] = *(const uint32_t*)(qh2 + qrow0 + (size_t)(gid + 8) * 64 + c0);
            qfh[kc][2] = *(const uint32_t*)(qh2 + qrow0 + (size_t)gid * 64 + c0 + 8);
            qfh[kc][3] = *(const uint32_t*)(qh2 + qrow0 + (size_t)(gid + 8) * 64 + c0 + 8);
            qfl[kc][0] = *(const uint32_t*)(ql2 + qrow0 + (size_t)gid * 64 + c0);
            qfl[kc][1] = *(const uint32_t*)(ql2 + qrow0 + (size_t)(gid + 8) * 64 + c0);
            qfl[kc][2] = *(const uint32_t*)(ql2 + qrow0 + (size_t)gid * 64 + c0 + 8);
            qfl[kc][3] = *(const uint32_t*)(ql2 + qrow0 + (size_t)(gid + 8) * 64 + c0 + 8);
        }
    }

    float m0 = -FLT_MAX, m1 = -FLT_MAX, l0 = 0.f, l1 = 0.f;
    float oacc[8][4];
    #pragma unroll
    for (int nt = 0; nt < 8; nt++)
        #pragma unroll
        for (int r = 0; r < 4; r++) oacc[nt][r] = 0.f;

    const int nkt = 4 * qt + 4;
    const int warp_max_row = qt * 128 + rb + 15;
    for (int kt = 0; kt < nkt; kt++) {
        {
            const __half* khb = kh2 + ((size_t)((b * HH + h) * SS + kt * 32)) * 64;
            int cc = tid >> 3, q4 = tid & 7;
            *(uint4*)&KsH[cc * KP2 + q4 * 4] = *(const uint4*)(khb + (size_t)cc * 64 + q4 * 8);

            int d = tid >> 2, v4 = tid & 3;
            const __half* vhb = vh2 + ((size_t)((b * HH + h) * 64 + d)) * SS + kt * 32;
            *(uint4*)&VsH[d * VP2 + v4 * 4] = *(const uint4*)(vhb + v4 * 8);
        }
        __syncthreads();

        if (kt * 32 <= warp_max_row) {   // per-warp causal early-out

        // ---- S = Q @ K^T (2-pass: ql*k + qh*k) ----
        float s[4][4];
        #pragma unroll
        for (int nt = 0; nt < 4; nt++)
            #pragma unroll
            for (int r = 0; r < 4; r++) s[nt][r] = 0.f;

        #pragma unroll
        for (int kc = 0; kc < 4; kc++) {
            uint32_t kb[4][2];
            #pragma unroll
            for (int nt = 0; nt < 4; nt++) {
                int cc = nt * 8 + gid;
                int w0 = kc * 8 + tig;
                kb[nt][0] = KsH[cc * KP2 + w0];
                kb[nt][1] = KsH[cc * KP2 + w0 + 4];
            }
            #pragma unroll
            for (int nt = 0; nt < 4; nt++) {
                mma_f16(s[nt], qfl[kc], kb[nt]);
                mma_f16(s[nt], qfh[kc], kb[nt]);
            }
        }

        // ---- causal mask ----
        if (32 * kt + 31 > qt * 128 + rb) {
            int row0 = qt * 128 + rb + gid;
            #pragma unroll
            for (int nt = 0; nt < 4; nt++) {
                int colb = kt * 32 + nt * 8 + 2 * tig;
                if (colb     > row0)     s[nt][0] = -1.0e30f;
                if (colb + 1 > row0)     s[nt][1] = -1.0e30f;
                if (colb     > row0 + 8) s[nt][2] = -1.0e30f;
                if (colb + 1 > row0 + 8) s[nt][3] = -1.0e30f;
            }
        }

        // ---- online softmax ----
        {
            float mx0 = -FLT_MAX, mx1 = -FLT_MAX;
            #pragma unroll
            for (int nt = 0; nt < 4; nt++) {
                mx0 = fmaxf(mx0, fmaxf(s[nt][0], s[nt][1]));
                mx1 = fmaxf(mx1, fmaxf(s[nt][2], s[nt][3]));
            }
            mx0 = fmaxf(mx0, __shfl_xor_sync(0xffffffffu, mx0, 1));
            mx0 = fmaxf(mx0, __shfl_xor_sync(0xffffffffu, mx0, 2));
            mx1 = fmaxf(mx1, __shfl_xor_sync(0xffffffffu, mx1, 1));
            mx1 = fmaxf(mx1, __shfl_xor_sync(0xffffffffu, mx1, 2));

            float mn0 = fmaxf(m0, mx0), mn1 = fmaxf(m1, mx1);
            float a0 = __expf(m0 - mn0), a1 = __expf(m1 - mn1);
            float rs0 = 0.f, rs1 = 0.f;
            #pragma unroll
            for (int nt = 0; nt < 4; nt++) {
                s[nt][0] = __expf(s[nt][0] - mn0);
                s[nt][1] = __expf(s[nt][1] - mn0);
                s[nt][2] = __expf(s[nt][2] - mn1);
                s[nt][3] = __expf(s[nt][3] - mn1);
                rs0 += s[nt][0] + s[nt][1];
                rs1 += s[nt][2] + s[nt][3];
            }
            rs0 += __shfl_xor_sync(0xffffffffu, rs0, 1);
            rs0 += __shfl_xor_sync(0xffffffffu, rs0, 2);
            rs1 += __shfl_xor_sync(0xffffffffu, rs1, 1);
            rs1 += __shfl_xor_sync(0xffffffffu, rs1, 2);
            l0 = l0 * a0 + rs0;  l1 = l1 * a1 + rs1;
            m0 = mn0;            m1 = mn1;
            #pragma unroll
            for (int nt = 0; nt < 8; nt++) {
                oacc[nt][0] *= a0; oacc[nt][1] *= a0;
                oacc[nt][2] *= a1; oacc[nt][3] *= a1;
            }
        }

        // ---- O += P @ V (2-pass: pl*v + ph*v; S fragments are PV A frags) ----
        #pragma unroll
        for (int ks2 = 0; ks2 < 2; ks2++) {
            uint32_t pah[4], pal[4];
            split_f16x2(s[2*ks2][0],   s[2*ks2][1],   pah[0], pal[0]);
            split_f16x2(s[2*ks2][2],   s[2*ks2][3],   pah[1], pal[1]);
            split_f16x2(s[2*ks2+1][0], s[2*ks2+1][1], pah[2], pal[2]);
            split_f16x2(s[2*ks2+1][2], s[2*ks2+1][3], pah[3], pal[3]);
            #pragma unroll
            for (int nt = 0; nt < 8; nt++) {
                int dn = nt * 8 + gid;
                int w0 = ks2 * 8 + tig;
                uint32_t vb[2];
                vb[0] = VsH[dn * VP2 + w0];
                vb[1] = VsH[dn * VP2 + w0 + 4];
                mma_f16(oacc[nt], pal, vb);
                mma_f16(oacc[nt], pah, vb);
            }
        }

        } // per-warp skip

        __syncthreads();
    }

    float inv0 = 1.0f / l0, inv1 = 1.0f / l1;
    float* ob = o + ((size_t)(b * SS + qt * 128 + rb)) * 512 + h * 64;
    #pragma unroll
    for (int nt = 0; nt < 8; nt++) {
        int col = nt * 8 + 2 * tig;
        *(float2*)(ob + (size_t)gid * 512 + col) =
            make_float2(oacc[nt][0] * inv0, oacc[nt][1] * inv0);
        *(float2*)(ob + (size_t)(gid + 8) * 512 + col) =
            make_float2(oacc[nt][2] * inv1, oacc[nt][3] * inv1);
    }
}

// ===========================================================================
// Launch. Input order: query, value, key_in, Wq, Wk, Wv, Wo.
// ===========================================================================
extern "C" void kernel_launch(void* const* d_in, const int* in_sizes, int n_in,
                              void* d_out, int out_size)
{
    const float* query  = (const float*)d_in[0];
    const float* value  = (const float*)d_in[1];
    const float* key_in = (const float*)d_in[2];
    const float* Wq     = (const float*)d_in[3];
    const float* Wk     = (const float*)d_in[4];
    const float* Wv     = (const float*)d_in[5];
    const float* Wo     = (const float*)d_in[6];
    float* out = (float*)d_out;

    float *q, *k, *v, *ao;
    __half *ah, *al, *bh;
    __half *qh2, *ql2, *kh2, *vh2;
    cudaGetSymbolAddress((void**)&q,  g_q);
    cudaGetSymbolAddress((void**)&k,  g_k);
    cudaGetSymbolAddress((void**)&v,  g_v);
    cudaGetSymbolAddress((void**)&ao, g_ao);
    cudaGetSymbolAddress((void**)&ah, g_ah);
    cudaGetSymbolAddress((void**)&al, g_al);
    cudaGetSymbolAddress((void**)&bh, g_bh);
    cudaGetSymbolAddress((void**)&qh2, g_qh2);
    cudaGetSymbolAddress((void**)&ql2, g_ql2);
    cudaGetSymbolAddress((void**)&kh2, g_kh2);
    cudaGetSymbolAddress((void**)&vh2, g_vh2);

    const int nA4 = MTOT * GK / 4;
    dim3 ggrid(MTOT / 128, GN / 128);       // (64, 4)
    dim3 wgrid(GK / 32, GN / 32);           // (16, 16)
    dim3 wblk(32, 8);

    // Q = query @ Wq ; K = key_in @ Wk ; V = value @ Wv
    wt_conv_kernel<<<wgrid, wblk>>>(Wq, bh);
    split_a_kernel<<<(nA4 + 255) / 256, 256>>>(query, ah, al, nA4);
    gemm_f16<<<ggrid, 256>>>(ah, al, bh, q);
    wt_conv_kernel<<<wgrid, wblk>>>(Wk, bh);
    split_a_kernel<<<(nA4 + 255) / 256, 256>>>(key_in, ah, al, nA4);
    gemm_f16<<<ggrid, 256>>>(ah, al, bh, k);
    wt_conv_kernel<<<wgrid, wblk>>>(Wv, bh);
    split_a_kernel<<<(nA4 + 255) / 256, 256>>>(value, ah, al, nA4);
    gemm_f16<<<ggrid, 256>>>(ah, al, bh, v);

    // rope+split q (hi/lo); rope+convert k; transpose+convert v
    const int nrope = BB * SS * HH * 32;
    rope_split_kernel<<<nrope / 256, 256>>>(q, qh2, ql2, 0.125f, nrope);
    rope_conv_kernel<<<nrope / 256, 256>>>(k, kh2, nrope);
    {
        dim3 vgrid(SS / 32, 2, BB * HH);
        v_conv_kernel<<<vgrid, wblk>>>(v, vh2);
    }

    dim3 agrid(SS / 128, BB * HH);          // (8, 64)
    attn_tc<<<agrid, 256>>>(qh2, ql2, kh2, vh2, ao);

    // out = ao @ Wo
    wt_conv_kernel<<<wgrid, wblk>>>(Wo, bh);
    split_a_kernel<<<(nA4 + 255) / 256, 256>>>(ao, ah, al, nA4);
    gemm_f16<<<ggrid, 256>>>(ah, al, bh, out);
}

// round 14
// speedup vs baseline: 3.8135x; 1.3377x over previous
#include <cuda_runtime.h>
#include <cuda_fp16.h>
#include <math.h>
#include <float.h>
#include <stdint.h>

// Problem constants
#define BB 8
#define SS 1024
#define DD 512
#define HH 8
#define MTOT (BB*SS)   // 8192
#define GK 512
#define GN 512

// Scratch (__device__ globals per allocation-free rule)
__device__ float g_q [BB*SS*DD];
__device__ float g_k [BB*SS*DD];
__device__ float g_v [BB*SS*DD];
__device__ float g_ao[BB*SS*DD];
__device__ __half g_a16[MTOT*GK];                    // fp16 activations
__device__ __half g_b16[GN*GK];                      // fp16 transposed W
// attention operands (all single fp16):
__device__ __half g_q16[BB*HH*SS*64];                // (b,h,s,d)
__device__ __half g_k16[BB*HH*SS*64];                // (b,h,s,d)
__device__ __half g_v16[BB*HH*64*SS];                // (b,h,d,s)

// ===========================================================================
// fp16 helpers (single-pass: both operands quantized, fp32 accumulate)
// ===========================================================================
__device__ __forceinline__ uint32_t pack_f16x2(float x0, float x1)
{
    __half2 H = __halves2half2(__float2half_rn(x0), __float2half_rn(x1));
    return *(uint32_t*)&H;
}

__device__ __forceinline__ void mma_f16(float* c, const uint32_t* a, const uint32_t* b)
{
    asm volatile(
        "mma.sync.aligned.m16n8k16.row.col.f32.f16.f16.f32 "
        "{%0,%1,%2,%3}, {%4,%5,%6,%7}, {%8,%9}, {%0,%1,%2,%3};\n"
        : "+f"(c[0]), "+f"(c[1]), "+f"(c[2]), "+f"(c[3])
        : "r"(a[0]), "r"(a[1]), "r"(a[2]), "r"(a[3]),
          "r"(b[0]), "r"(b[1]));
}

// ===========================================================================
// Prep kernels
// ===========================================================================
// Activations f32 -> fp16.
__global__ void a_conv_kernel(const float* __restrict__ x,
                              __half* __restrict__ y, int n4)
{
    int idx = blockIdx.x * blockDim.x + threadIdx.x;
    if (idx >= n4) return;
    float4 v = ((const float4*)x)[idx];
    ((uint2*)y)[idx] = make_uint2(pack_f16x2(v.x, v.y), pack_f16x2(v.z, v.w));
}

// W [K,N] f32 -> fp16 transposed [N,K]; coalesced via 32x32 smem tiles.
__global__ void wt_conv_kernel(const float* __restrict__ w,
                               __half* __restrict__ y)
{
    __shared__ float tile[32][33];
    const int k0 = blockIdx.x * 32, n0 = blockIdx.y * 32;
    const int tx = threadIdx.x, ty = threadIdx.y;   // (32, 8)
    #pragma unroll
    for (int j = 0; j < 4; j++)
        tile[ty + j * 8][tx] = w[(size_t)(k0 + ty + j * 8) * GN + n0 + tx];
    __syncthreads();
    #pragma unroll
    for (int j = 0; j < 4; j++) {
        int nn = n0 + ty + j * 8;
        int kk = k0 + tx;
        y[(size_t)nn * GK + kk] = __float2half_rn(tile[tx][ty + j * 8]);
    }
}

// RoPE + optional scale + fp16; (b,s,h,d) f32 -> (b,h,s,d).
__global__ void rope_conv_kernel(const float* __restrict__ x,
                                 __half* __restrict__ y,
                                 float scale, int n)
{
    int idx = blockIdx.x * blockDim.x + threadIdx.x;
    if (idx >= n) return;
    int i   = idx & 31;
    int row = idx >> 5;                 // (b*S+s)*H + h
    int s   = (row >> 3) & (SS - 1);
    int h   = row & 7;
    int b   = row >> 13;

    float inv_freq = powf(10000.0f, -(float)i * (1.0f / 32.0f));
    float ang = (float)s * inv_freq;
    float sn, cs;
    sincosf(ang, &sn, &cs);

    const float* p = x + (size_t)row * 64;
    float x1 = p[i], x2 = p[i + 32];
    size_t orow = ((size_t)((b * HH + h) * SS + s)) * 64;
    y[orow + i]      = __float2half_rn((x1 * cs - x2 * sn) * scale);
    y[orow + i + 32] = __float2half_rn((x2 * cs + x1 * sn) * scale);
}

// V transpose + fp16: (b,s,h,d) f32 -> (b,h,d,s). 32x32 smem tiles.
__global__ void v_conv_kernel(const float* __restrict__ v,
                              __half* __restrict__ y)
{
    __shared__ float tile[32][33];
    const int bh = blockIdx.z;
    const int b = bh >> 3, h = bh & 7;
    const int s0 = blockIdx.x * 32, d0 = blockIdx.y * 32;
    const int tx = threadIdx.x, ty = threadIdx.y;   // (32, 8)

    #pragma unroll
    for (int j = 0; j < 4; j++) {
        int s = s0 + ty + j * 8;
        tile[ty + j * 8][tx] =
            v[((size_t)(b * SS + s) * HH + h) * 64 + d0 + tx];
    }
    __syncthreads();
    #pragma unroll
    for (int j = 0; j < 4; j++) {
        int d = d0 + ty + j * 8;
        size_t oi = ((size_t)((b * HH + h) * 64 + d)) * SS + s0 + tx;
        y[oi] = __float2half_rn(tile[tx][ty + j * 8]);
    }
}

// ===========================================================================
// GEMM: C[M,N] = A16 @ B16^T, fp16 m16n8k16 single-pass.
// BM=BN=128, BK=32. 256 threads = 8 warps (2x4): warp tile 64(m) x 32(n).
// Smem rows: [row][20 words] (32 fp16 + pad), conflict-free fragment loads.
// ===========================================================================
#define GP 20
__global__ __launch_bounds__(256) void gemm_f16(
    const __half* __restrict__ A, const __half* __restrict__ B,
    float* __restrict__ C)
{
    __shared__ uint32_t As[128 * GP], Bs[128 * GP];   // 2 x 10240B = 20KB

    const int tid  = threadIdx.x;
    const int lane = tid & 31;
    const int wid  = tid >> 5;
    const int gid  = lane >> 2;
    const int tig  = lane & 3;
    const int wm   = wid >> 2;
    const int wn   = wid & 3;
    const int bm   = blockIdx.x * 128;
    const int bn   = blockIdx.y * 128;

    float c[4][4][4];
    #pragma unroll
    for (int tm = 0; tm < 4; tm++)
        #pragma unroll
        for (int tn = 0; tn < 4; tn++)
            #pragma unroll
            for (int r = 0; r < 4; r++) c[tm][tn][r] = 0.f;

    for (int k0 = 0; k0 < GK; k0 += 32) {
        // 2 tiles x 512 uint4; 2 per thread per tile.
        #pragma unroll
        for (int p = 0; p < 2; p++) {
            int e = tid + p * 256;
            int r = e >> 2, cc = e & 3;
            size_t ga = (size_t)(bm + r) * GK + k0 + cc * 8;
            size_t gb = (size_t)(bn + r) * GK + k0 + cc * 8;
            *(uint4*)&As[r * GP + cc * 4] = *(const uint4*)(A + ga);
            *(uint4*)&Bs[r * GP + cc * 4] = *(const uint4*)(B + gb);
        }
        __syncthreads();

        #pragma unroll
        for (int ks = 0; ks < 2; ks++) {
            uint32_t af[4][4], bf[4][2];
            #pragma unroll
            for (int tm = 0; tm < 4; tm++) {
                int mr = wm * 64 + tm * 16 + gid;
                int w0 = ks * 8 + tig;
                af[tm][0] = As[mr * GP + w0];
                af[tm][1] = As[(mr + 8) * GP + w0];
                af[tm][2] = As[mr * GP + w0 + 4];
                af[tm][3] = As[(mr + 8) * GP + w0 + 4];
            }
            #pragma unroll
            for (int tn = 0; tn < 4; tn++) {
                int nc = wn * 32 + tn * 8 + gid;
                int w0 = ks * 8 + tig;
                bf[tn][0] = Bs[nc * GP + w0];
                bf[tn][1] = Bs[nc * GP + w0 + 4];
            }
            #pragma unroll
            for (int tm = 0; tm < 4; tm++)
                #pragma unroll
                for (int tn = 0; tn < 4; tn++)
                    mma_f16(c[tm][tn], af[tm], bf[tn]);
        }
        __syncthreads();
    }

    #pragma unroll
    for (int tm = 0; tm < 4; tm++)
        #pragma unroll
        for (int tn = 0; tn < 4; tn++) {
            int row = bm + wm * 64 + tm * 16 + gid;
            int col = bn + wn * 32 + tn * 8 + 2 * tig;
            *(float2*)(C + (size_t)row * GN + col) =
                make_float2(c[tm][tn][0], c[tm][tn][1]);
            *(float2*)(C + (size_t)(row + 8) * GN + col) =
                make_float2(c[tm][tn][2], c[tm][tn][3]);
        }
}

// ===========================================================================
// Causal flash attention, fp16 m16n8k16 single-pass.
// Block = (qt, b*h): Br=128 q rows, Bc=32 keys/tile. 8 warps x 16 rows.
// S fragments reused directly as PV A fragments (no P smem).
// ===========================================================================
#define KP2 36
#define VP2 20
__global__ __launch_bounds__(256) void attn_tc(
    const __half* __restrict__ q16, const __half* __restrict__ k16,
    const __half* __restrict__ v16, float* __restrict__ o)
{
    __shared__ uint32_t Ks[32 * KP2];
    __shared__ uint32_t Vs[64 * VP2];

    const int qt   = (int)gridDim.x - 1 - (int)blockIdx.x;
    const int bh   = blockIdx.y;
    const int b    = bh >> 3, h = bh & 7;
    const int tid  = threadIdx.x;
    const int lane = tid & 31;
    const int w    = tid >> 5;
    const int gid  = lane >> 2;
    const int tig  = lane & 3;
    const int rb   = w * 16;

    uint32_t qf[4][4];
    {
        const size_t qrow0 = ((size_t)((b * HH + h) * SS + qt * 128 + rb)) * 64;
        #pragma unroll
        for (int kc = 0; kc < 4; kc++) {
            int c0 = kc * 16 + 2 * tig;
            qf[kc][0] = *(const uint32_t*)(q16 + qrow0 + (size_t)gid * 64 + c0);
            qf[kc][1] = *(const uint32_t*)(q16 + qrow0 + (size_t)(gid + 8) * 64 + c0);
            qf[kc][2] = *(const uint32_t*)(q16 + qrow0 + (size_t)gid * 64 + c0 + 8);
            qf[kc][3] = *(const uint32_t*)(q16 + qrow0 + (size_t)(gid + 8) * 64 + c0 + 8);
        }
    }

    float m0 = -FLT_MAX, m1 = -FLT_MAX, l0 = 0.f, l1 = 0.f;
    float oacc[8][4];
    #pragma unroll
    for (int nt = 0; nt < 8; nt++)
        #pragma unroll
        for (int r = 0; r < 4; r++) oacc[nt][r] = 0.f;

    const int nkt = 4 * qt + 4;
    const int warp_max_row = qt * 128 + rb + 15;
    for (int kt = 0; kt < nkt; kt++) {
        {
            const __half* khb = k16 + ((size_t)((b * HH + h) * SS + kt * 32)) * 64;
            int cc = tid >> 3, q4 = tid & 7;
            *(uint4*)&Ks[cc * KP2 + q4 * 4] = *(const uint4*)(khb + (size_t)cc * 64 + q4 * 8);

            int d = tid >> 2, v4 = tid & 3;
            const __half* vhb = v16 + ((size_t)((b * HH + h) * 64 + d)) * SS + kt * 32;
            *(uint4*)&Vs[d * VP2 + v4 * 4] = *(const uint4*)(vhb + v4 * 8);
        }
        __syncthreads();

        if (kt * 32 <= warp_max_row) {   // per-warp causal early-out

        // ---- S = Q @ K^T ----
        float s[4][4];
        #pragma unroll
        for (int nt = 0; nt < 4; nt++)
            #pragma unroll
            for (int r = 0; r < 4; r++) s[nt][r] = 0.f;

        #pragma unroll
        for (int kc = 0; kc < 4; kc++) {
            uint32_t kb[4][2];
            #pragma unroll
            for (int nt = 0; nt < 4; nt++) {
                int cc = nt * 8 + gid;
                int w0 = kc * 8 + tig;
                kb[nt][0] = Ks[cc * KP2 + w0];
                kb[nt][1] = Ks[cc * KP2 + w0 + 4];
            }
            #pragma unroll
            for (int nt = 0; nt < 4; nt++)
                mma_f16(s[nt], qf[kc], kb[nt]);
        }

        // ---- causal mask ----
        if (32 * kt + 31 > qt * 128 + rb) {
            int row0 = qt * 128 + rb + gid;
            #pragma unroll
            for (int nt = 0; nt < 4; nt++) {
                int colb = kt * 32 + nt * 8 + 2 * tig;
                if (colb     > row0)     s[nt][0] = -1.0e30f;
                if (colb + 1 > row0)     s[nt][1] = -1.0e30f;
                if (colb     > row0 + 8) s[nt][2] = -1.0e30f;
                if (colb + 1 > row0 + 8) s[nt][3] = -1.0e30f;
            }
        }

        // ---- online softmax ----
        {
            float mx0 = -FLT_MAX, mx1 = -FLT_MAX;
            #pragma unroll
            for (int nt = 0; nt < 4; nt++) {
                mx0 = fmaxf(mx0, fmaxf(s[nt][0], s[nt][1]));
                mx1 = fmaxf(mx1, fmaxf(s[nt][2], s[nt][3]));
            }
            mx0 = fmaxf(mx0, __shfl_xor_sync(0xffffffffu, mx0, 1));
            mx0 = fmaxf(mx0, __shfl_xor_sync(0xffffffffu, mx0, 2));
            mx1 = fmaxf(mx1, __shfl_xor_sync(0xffffffffu, mx1, 1));
            mx1 = fmaxf(mx1, __shfl_xor_sync(0xffffffffu, mx1, 2));

            float mn0 = fmaxf(m0, mx0), mn1 = fmaxf(m1, mx1);
            float a0 = __expf(m0 - mn0), a1 = __expf(m1 - mn1);
            float rs0 = 0.f, rs1 = 0.f;
            #pragma unroll
            for (int nt = 0; nt < 4; nt++) {
                s[nt][0] = __expf(s[nt][0] - mn0);
                s[nt][1] = __expf(s[nt][1] - mn0);
                s[nt][2] = __expf(s[nt][2] - mn1);
                s[nt][3] = __expf(s[nt][3] - mn1);
                rs0 += s[nt][0] + s[nt][1];
                rs1 += s[nt][2] + s[nt][3];
            }
            rs0 += __shfl_xor_sync(0xffffffffu, rs0, 1);
            rs0 += __shfl_xor_sync(0xffffffffu, rs0, 2);
            rs1 += __shfl_xor_sync(0xffffffffu, rs1, 1);
            rs1 += __shfl_xor_sync(0xffffffffu, rs1, 2);
            l0 = l0 * a0 + rs0;  l1 = l1 * a1 + rs1;
            m0 = mn0;            m1 = mn1;
            #pragma unroll
            for (int nt = 0; nt < 8; nt++) {
                oacc[nt][0] *= a0; oacc[nt][1] *= a0;
                oacc[nt][2] *= a1; oacc[nt][3] *= a1;
            }
        }

        // ---- O += P @ V (S fragments are PV A fragments; pack to fp16) ----
        #pragma unroll
        for (int ks2 = 0; ks2 < 2; ks2++) {
            uint32_t pa[4];
            pa[0] = pack_f16x2(s[2*ks2][0],   s[2*ks2][1]);
            pa[1] = pack_f16x2(s[2*ks2][2],   s[2*ks2][3]);
            pa[2] = pack_f16x2(s[2*ks2+1][0], s[2*ks2+1][1]);
            pa[3] = pack_f16x2(s[2*ks2+1][2], s[2*ks2+1][3]);
            #pragma unroll
            for (int nt = 0; nt < 8; nt++) {
                int dn = nt * 8 + gid;
                int w0 = ks2 * 8 + tig;
                uint32_t vb[2];
                vb[0] = Vs[dn * VP2 + w0];
                vb[1] = Vs[dn * VP2 + w0 + 4];
                mma_f16(oacc[nt], pa, vb);
            }
        }

        } // per-warp skip

        __syncthreads();
    }

    float inv0 = 1.0f / l0, inv1 = 1.0f / l1;
    float* ob = o + ((size_t)(b * SS + qt * 128 + rb)) * 512 + h * 64;
    #pragma unroll
    for (int nt = 0; nt < 8; nt++) {
        int col = nt * 8 + 2 * tig;
        *(float2*)(ob + (size_t)gid * 512 + col) =
            make_float2(oacc[nt][0] * inv0, oacc[nt][1] * inv0);
        *(float2*)(ob + (size_t)(gid + 8) * 512 + col) =
            make_float2(oacc[nt][2] * inv1, oacc[nt][3] * inv1);
    }
}

// ===========================================================================
// Launch. Input order: query, value, key_in, Wq, Wk, Wv, Wo.
// ===========================================================================
extern "C" void kernel_launch(void* const* d_in, const int* in_sizes, int n_in,
                              void* d_out, int out_size)
{
    const float* query  = (const float*)d_in[0];
    const float* value  = (const float*)d_in[1];
    const float* key_in = (const float*)d_in[2];
    const float* Wq     = (const float*)d_in[3];
    const float* Wk     = (const float*)d_in[4];
    const float* Wv     = (const float*)d_in[5];
    const float* Wo     = (const float*)d_in[6];
    float* out = (float*)d_out;

    float *q, *k, *v, *ao;
    __half *a16, *b16, *q16, *k16, *v16;
    cudaGetSymbolAddress((void**)&q,  g_q);
    cudaGetSymbolAddress((void**)&k,  g_k);
    cudaGetSymbolAddress((void**)&v,  g_v);
    cudaGetSymbolAddress((void**)&ao, g_ao);
    cudaGetSymbolAddress((void**)&a16, g_a16);
    cudaGetSymbolAddress((void**)&b16, g_b16);
    cudaGetSymbolAddress((void**)&q16, g_q16);
    cudaGetSymbolAddress((void**)&k16, g_k16);
    cudaGetSymbolAddress((void**)&v16, g_v16);

    const int nA4 = MTOT * GK / 4;
    dim3 ggrid(MTOT / 128, GN / 128);       // (64, 4)
    dim3 wgrid(GK / 32, GN / 32);           // (16, 16)
    dim3 wblk(32, 8);

    // Q = query @ Wq ; K = key_in @ Wk ; V = value @ Wv
    wt_conv_kernel<<<wgrid, wblk>>>(Wq, b16);
    a_conv_kernel<<<(nA4 + 255) / 256, 256>>>(query, a16, nA4);
    gemm_f16<<<ggrid, 256>>>(a16, b16, q);
    wt_conv_kernel<<<wgrid, wblk>>>(Wk, b16);
    a_conv_kernel<<<(nA4 + 255) / 256, 256>>>(key_in, a16, nA4);
    gemm_f16<<<ggrid, 256>>>(a16, b16, k);
    wt_conv_kernel<<<wgrid, wblk>>>(Wv, b16);
    a_conv_kernel<<<(nA4 + 255) / 256, 256>>>(value, a16, nA4);
    gemm_f16<<<ggrid, 256>>>(a16, b16, v);

    // rope+convert q/k ; transpose+convert v
    const int nrope = BB * SS * HH * 32;
    rope_conv_kernel<<<nrope / 256, 256>>>(q, q16, 0.125f, nrope);
    rope_conv_kernel<<<nrope / 256, 256>>>(k, k16, 1.0f, nrope);
    {
        dim3 vgrid(SS / 32, 2, BB * HH);
        v_conv_kernel<<<vgrid, wblk>>>(v, v16);
    }

    dim3 agrid(SS / 128, BB * HH);          // (8, 64)
    attn_tc<<<agrid, 256>>>(q16, k16, v16, ao);

    // out = ao @ Wo
    wt_conv_kernel<<<wgrid, wblk>>>(Wo, b16);
    a_conv_kernel<<<(nA4 + 255) / 256, 256>>>(ao, a16, nA4);
    gemm_f16<<<ggrid, 256>>>(a16, b16, out);
}

// round 15
// speedup vs baseline: 4.4895x; 1.1772x over previous
#include <cuda_runtime.h>
#include <cuda_fp16.h>
#include <math.h>
#include <float.h>
#include <stdint.h>

// Problem constants
#define BB 8
#define SS 1024
#define DD 512
#define HH 8
#define MTOT (BB*SS)   // 8192
#define GK 512
#define GN 512

// Scratch (__device__ globals per allocation-free rule)
__device__ float g_q [BB*SS*DD];
__device__ float g_k [BB*SS*DD];
__device__ float g_v [BB*SS*DD];
__device__ __half g_a16[MTOT*GK];                    // fp16 activations / attn out
__device__ __half g_b16[4*GN*GK];                    // fp16 transposed W x4
__device__ __half g_q16[BB*HH*SS*64];                // (b,h,s,d)
__device__ __half g_k16[BB*HH*SS*64];                // (b,h,s,d)
__device__ __half g_v16[BB*HH*64*SS];                // (b,h,d,s)

// ===========================================================================
// helpers
// ===========================================================================
__device__ __forceinline__ uint32_t smem_u32(const void* p) {
    uint32_t a;
    asm("{ .reg .u64 t; cvta.to.shared.u64 t, %1; cvt.u32.u64 %0, t; }"
        : "=r"(a) : "l"(p));
    return a;
}
__device__ __forceinline__ void cp_async16(uint32_t saddr, const void* gptr) {
    asm volatile("cp.async.cg.shared.global [%0], [%1], 16;"
                 :: "r"(saddr), "l"(gptr));
}
#define CP_COMMIT() asm volatile("cp.async.commit_group;" ::: "memory")
#define CP_WAIT1()  asm volatile("cp.async.wait_group 1;" ::: "memory")
#define CP_WAIT0()  asm volatile("cp.async.wait_group 0;" ::: "memory")

__device__ __forceinline__ uint32_t pack_f16x2(float x0, float x1)
{
    __half2 H = __halves2half2(__float2half_rn(x0), __float2half_rn(x1));
    return *(uint32_t*)&H;
}

__device__ __forceinline__ void mma_f16(float* c, const uint32_t* a, const uint32_t* b)
{
    asm volatile(
        "mma.sync.aligned.m16n8k16.row.col.f32.f16.f16.f32 "
        "{%0,%1,%2,%3}, {%4,%5,%6,%7}, {%8,%9}, {%0,%1,%2,%3};\n"
        : "+f"(c[0]), "+f"(c[1]), "+f"(c[2]), "+f"(c[3])
        : "r"(a[0]), "r"(a[1]), "r"(a[2]), "r"(a[3]),
          "r"(b[0]), "r"(b[1]));
}

// ===========================================================================
// Prep kernels
// ===========================================================================
__global__ void a_conv_kernel(const float* __restrict__ x,
                              __half* __restrict__ y, int n4)
{
    int idx = blockIdx.x * blockDim.x + threadIdx.x;
    if (idx >= n4) return;
    float4 v = ((const float4*)x)[idx];
    ((uint2*)y)[idx] = make_uint2(pack_f16x2(v.x, v.y), pack_f16x2(v.z, v.w));
}

// All 4 weights [K,N] f32 -> fp16 transposed [N,K], one launch (z = which W).
__global__ void wt_conv_all(const float* __restrict__ w0,
                            const float* __restrict__ w1,
                            const float* __restrict__ w2,
                            const float* __restrict__ w3,
                            __half* __restrict__ y)
{
    __shared__ float tile[32][33];
    const int z = blockIdx.z;
    const float* w = (z == 0) ? w0 : (z == 1) ? w1 : (z == 2) ? w2 : w3;
    __half* yz = y + (size_t)z * GN * GK;
    const int k0 = blockIdx.x * 32, n0 = blockIdx.y * 32;
    const int tx = threadIdx.x, ty = threadIdx.y;   // (32, 8)
    #pragma unroll
    for (int j = 0; j < 4; j++)
        tile[ty + j * 8][tx] = w[(size_t)(k0 + ty + j * 8) * GN + n0 + tx];
    __syncthreads();
    #pragma unroll
    for (int j = 0; j < 4; j++) {
        int nn = n0 + ty + j * 8;
        int kk = k0 + tx;
        yz[(size_t)nn * GK + kk] = __float2half_rn(tile[tx][ty + j * 8]);
    }
}

// RoPE + optional scale + fp16; (b,s,h,d) f32 -> (b,h,s,d).
__global__ void rope_conv_kernel(const float* __restrict__ x,
                                 __half* __restrict__ y,
                                 float scale, int n)
{
    int idx = blockIdx.x * blockDim.x + threadIdx.x;
    if (idx >= n) return;
    int i   = idx & 31;
    int row = idx >> 5;
    int s   = (row >> 3) & (SS - 1);
    int h   = row & 7;
    int b   = row >> 13;

    float inv_freq = powf(10000.0f, -(float)i * (1.0f / 32.0f));
    float ang = (float)s * inv_freq;
    float sn, cs;
    sincosf(ang, &sn, &cs);

    const float* p = x + (size_t)row * 64;
    float x1 = p[i], x2 = p[i + 32];
    size_t orow = ((size_t)((b * HH + h) * SS + s)) * 64;
    y[orow + i]      = __float2half_rn((x1 * cs - x2 * sn) * scale);
    y[orow + i + 32] = __float2half_rn((x2 * cs + x1 * sn) * scale);
}

// V transpose + fp16: (b,s,h,d) f32 -> (b,h,d,s). 32x32 smem tiles.
__global__ void v_conv_kernel(const float* __restrict__ v,
                              __half* __restrict__ y)
{
    __shared__ float tile[32][33];
    const int bh = blockIdx.z;
    const int b = bh >> 3, h = bh & 7;
    const int s0 = blockIdx.x * 32, d0 = blockIdx.y * 32;
    const int tx = threadIdx.x, ty = threadIdx.y;   // (32, 8)

    #pragma unroll
    for (int j = 0; j < 4; j++) {
        int s = s0 + ty + j * 8;
        tile[ty + j * 8][tx] =
            v[((size_t)(b * SS + s) * HH + h) * 64 + d0 + tx];
    }
    __syncthreads();
    #pragma unroll
    for (int j = 0; j < 4; j++) {
        int d = d0 + ty + j * 8;
        size_t oi = ((size_t)((b * HH + h) * 64 + d)) * SS + s0 + tx;
        y[oi] = __float2half_rn(tile[tx][ty + j * 8]);
    }
}

// ===========================================================================
// GEMM: C[M,N] = A16 @ B16^T, fp16 m16n8k16, cp.async 2-stage pipeline.
// BM=BN=128, BK=32. 256 threads = 8 warps (2x4): warp tile 64(m) x 32(n).
// C written fp32 (for rope/v paths) OR fp16 handled by caller variant flag.
// ===========================================================================
#define GP 20
template <bool OUT16>
__global__ __launch_bounds__(256) void gemm_f16(
    const __half* __restrict__ A, const __half* __restrict__ B,
    float* __restrict__ C, __half* __restrict__ C16)
{
    __shared__ uint32_t As[2][128 * GP], Bs[2][128 * GP];   // 40KB

    const int tid  = threadIdx.x;
    const int lane = tid & 31;
    const int wid  = tid >> 5;
    const int gid  = lane >> 2;
    const int tig  = lane & 3;
    const int wm   = wid >> 2;
    const int wn   = wid & 3;
    const int bm   = blockIdx.x * 128;
    const int bn   = blockIdx.y * 128;

    const int r0 = tid >> 2, cc0 = tid & 3;       // load mapping (p=0)
    const int r1 = (tid + 256) >> 2, cc1 = (tid + 256) & 3;

    float c[4][4][4];
    #pragma unroll
    for (int tm = 0; tm < 4; tm++)
        #pragma unroll
        for (int tn = 0; tn < 4; tn++)
            #pragma unroll
            for (int r = 0; r < 4; r++) c[tm][tn][r] = 0.f;

    // issue stage 0
    {
        cp_async16(smem_u32(&As[0][r0 * GP + cc0 * 4]), A + (size_t)(bm + r0) * GK + cc0 * 8);
        cp_async16(smem_u32(&Bs[0][r0 * GP + cc0 * 4]), B + (size_t)(bn + r0) * GK + cc0 * 8);
        cp_async16(smem_u32(&As[0][r1 * GP + cc1 * 4]), A + (size_t)(bm + r1) * GK + cc1 * 8);
        cp_async16(smem_u32(&Bs[0][r1 * GP + cc1 * 4]), B + (size_t)(bn + r1) * GK + cc1 * 8);
        CP_COMMIT();
    }

    for (int it = 0; it < 16; it++) {
        const int st = it & 1;
        if (it < 15) {
            const int ns = st ^ 1;
            const int k0n = (it + 1) * 32;
            cp_async16(smem_u32(&As[ns][r0 * GP + cc0 * 4]), A + (size_t)(bm + r0) * GK + k0n + cc0 * 8);
            cp_async16(smem_u32(&Bs[ns][r0 * GP + cc0 * 4]), B + (size_t)(bn + r0) * GK + k0n + cc0 * 8);
            cp_async16(smem_u32(&As[ns][r1 * GP + cc1 * 4]), A + (size_t)(bm + r1) * GK + k0n + cc1 * 8);
            cp_async16(smem_u32(&Bs[ns][r1 * GP + cc1 * 4]), B + (size_t)(bn + r1) * GK + k0n + cc1 * 8);
            CP_COMMIT();
            CP_WAIT1();
        } else {
            CP_WAIT0();
        }
        __syncthreads();

        #pragma unroll
        for (int ks = 0; ks < 2; ks++) {
            uint32_t af[4][4], bf[4][2];
            #pragma unroll
            for (int tm = 0; tm < 4; tm++) {
                int mr = wm * 64 + tm * 16 + gid;
                int w0 = ks * 8 + tig;
                af[tm][0] = As[st][mr * GP + w0];
                af[tm][1] = As[st][(mr + 8) * GP + w0];
                af[tm][2] = As[st][mr * GP + w0 + 4];
                af[tm][3] = As[st][(mr + 8) * GP + w0 + 4];
            }
            #pragma unroll
            for (int tn = 0; tn < 4; tn++) {
                int nc = wn * 32 + tn * 8 + gid;
                int w0 = ks * 8 + tig;
                bf[tn][0] = Bs[st][nc * GP + w0];
                bf[tn][1] = Bs[st][nc * GP + w0 + 4];
            }
            #pragma unroll
            for (int tm = 0; tm < 4; tm++)
                #pragma unroll
                for (int tn = 0; tn < 4; tn++)
                    mma_f16(c[tm][tn], af[tm], bf[tn]);
        }
        __syncthreads();   // protect stage st before it is refilled at it+1
    }

    #pragma unroll
    for (int tm = 0; tm < 4; tm++)
        #pragma unroll
        for (int tn = 0; tn < 4; tn++) {
            int row = bm + wm * 64 + tm * 16 + gid;
            int col = bn + wn * 32 + tn * 8 + 2 * tig;
            if (OUT16) {
                *(uint32_t*)(C16 + (size_t)row * GN + col) =
                    pack_f16x2(c[tm][tn][0], c[tm][tn][1]);
                *(uint32_t*)(C16 + (size_t)(row + 8) * GN + col) =
                    pack_f16x2(c[tm][tn][2], c[tm][tn][3]);
            } else {
                *(float2*)(C + (size_t)row * GN + col) =
                    make_float2(c[tm][tn][0], c[tm][tn][1]);
                *(float2*)(C + (size_t)(row + 8) * GN + col) =
                    make_float2(c[tm][tn][2], c[tm][tn][3]);
            }
        }
}

// ===========================================================================
// Causal flash attention, fp16 single-pass, cp.async 2-stage K/V pipeline.
// Output written as fp16 directly into final-GEMM A layout (b*S+s, h*64+d).
// ===========================================================================
#define KP2 36
#define VP2 20
__global__ __launch_bounds__(256) void attn_tc(
    const __half* __restrict__ q16, const __half* __restrict__ k16,
    const __half* __restrict__ v16, __half* __restrict__ o16)
{
    __shared__ uint32_t Ks[2][32 * KP2];
    __shared__ uint32_t Vs[2][64 * VP2];

    const int qt   = (int)gridDim.x - 1 - (int)blockIdx.x;
    const int bh   = blockIdx.y;
    const int b    = bh >> 3, h = bh & 7;
    const int tid  = threadIdx.x;
    const int lane = tid & 31;
    const int w    = tid >> 5;
    const int gid  = lane >> 2;
    const int tig  = lane & 3;
    const int rb   = w * 16;

    // load mappings for K (32x64 fp16) and V (64x32 fp16): 1 uint4 each/thread
    const int kcc = tid >> 3, kq4 = tid & 7;
    const int vdd = tid >> 2, vv4 = tid & 3;
    const __half* kbase = k16 + ((size_t)((b * HH + h) * SS)) * 64;
    const __half* vbase = v16 + ((size_t)((b * HH + h) * 64 + vdd)) * SS;

    uint32_t qf[4][4];
    {
        const size_t qrow0 = ((size_t)((b * HH + h) * SS + qt * 128 + rb)) * 64;
        #pragma unroll
        for (int kc = 0; kc < 4; kc++) {
            int c0 = kc * 16 + 2 * tig;
            qf[kc][0] = *(const uint32_t*)(q16 + qrow0 + (size_t)gid * 64 + c0);
            qf[kc][1] = *(const uint32_t*)(q16 + qrow0 + (size_t)(gid + 8) * 64 + c0);
            qf[kc][2] = *(const uint32_t*)(q16 + qrow0 + (size_t)gid * 64 + c0 + 8);
            qf[kc][3] = *(const uint32_t*)(q16 + qrow0 + (size_t)(gid + 8) * 64 + c0 + 8);
        }
    }

    float m0 = -FLT_MAX, m1 = -FLT_MAX, l0 = 0.f, l1 = 0.f;
    float oacc[8][4];
    #pragma unroll
    for (int nt = 0; nt < 8; nt++)
        #pragma unroll
        for (int r = 0; r < 4; r++) oacc[nt][r] = 0.f;

    const int nkt = 4 * qt + 4;
    const int warp_max_row = qt * 128 + rb + 15;

    // issue stage 0
    cp_async16(smem_u32(&Ks[0][kcc * KP2 + kq4 * 4]),
               kbase + (size_t)kcc * 64 + kq4 * 8);
    cp_async16(smem_u32(&Vs[0][vdd * VP2 + vv4 * 4]),
               vbase + vv4 * 8);
    CP_COMMIT();

    for (int kt = 0; kt < nkt; kt++) {
        const int st = kt & 1;
        if (kt < nkt - 1) {
            const int ns = st ^ 1;
            cp_async16(smem_u32(&Ks[ns][kcc * KP2 + kq4 * 4]),
                       kbase + ((size_t)(kt + 1) * 32 + kcc) * 64 + kq4 * 8);
            cp_async16(smem_u32(&Vs[ns][vdd * VP2 + vv4 * 4]),
                       vbase + (size_t)(kt + 1) * 32 + vv4 * 8);
            CP_COMMIT();
            CP_WAIT1();
        } else {
            CP_WAIT0();
        }
        __syncthreads();

        if (kt * 32 <= warp_max_row) {   // per-warp causal early-out

        // ---- S = Q @ K^T ----
        float s[4][4];
        #pragma unroll
        for (int nt = 0; nt < 4; nt++)
            #pragma unroll
            for (int r = 0; r < 4; r++) s[nt][r] = 0.f;

        #pragma unroll
        for (int kc = 0; kc < 4; kc++) {
            uint32_t kb[4][2];
            #pragma unroll
            for (int nt = 0; nt < 4; nt++) {
                int cc = nt * 8 + gid;
                int w0 = kc * 8 + tig;
                kb[nt][0] = Ks[st][cc * KP2 + w0];
                kb[nt][1] = Ks[st][cc * KP2 + w0 + 4];
            }
            #pragma unroll
            for (int nt = 0; nt < 4; nt++)
                mma_f16(s[nt], qf[kc], kb[nt]);
        }

        // ---- causal mask ----
        if (32 * kt + 31 > qt * 128 + rb) {
            int row0 = qt * 128 + rb + gid;
            #pragma unroll
            for (int nt = 0; nt < 4; nt++) {
                int colb = kt * 32 + nt * 8 + 2 * tig;
                if (colb     > row0)     s[nt][0] = -1.0e30f;
                if (colb + 1 > row0)     s[nt][1] = -1.0e30f;
                if (colb     > row0 + 8) s[nt][2] = -1.0e30f;
                if (colb + 1 > row0 + 8) s[nt][3] = -1.0e30f;
            }
        }

        // ---- online softmax ----
        {
            float mx0 = -FLT_MAX, mx1 = -FLT_MAX;
            #pragma unroll
            for (int nt = 0; nt < 4; nt++) {
                mx0 = fmaxf(mx0, fmaxf(s[nt][0], s[nt][1]));
                mx1 = fmaxf(mx1, fmaxf(s[nt][2], s[nt][3]));
            }
            mx0 = fmaxf(mx0, __shfl_xor_sync(0xffffffffu, mx0, 1));
            mx0 = fmaxf(mx0, __shfl_xor_sync(0xffffffffu, mx0, 2));
            mx1 = fmaxf(mx1, __shfl_xor_sync(0xffffffffu, mx1, 1));
            mx1 = fmaxf(mx1, __shfl_xor_sync(0xffffffffu, mx1, 2));

            float mn0 = fmaxf(m0, mx0), mn1 = fmaxf(m1, mx1);
            float a0 = __expf(m0 - mn0), a1 = __expf(m1 - mn1);
            float rs0 = 0.f, rs1 = 0.f;
            #pragma unroll
            for (int nt = 0; nt < 4; nt++) {
                s[nt][0] = __expf(s[nt][0] - mn0);
                s[nt][1] = __expf(s[nt][1] - mn0);
                s[nt][2] = __expf(s[nt][2] - mn1);
                s[nt][3] = __expf(s[nt][3] - mn1);
                rs0 += s[nt][0] + s[nt][1];
                rs1 += s[nt][2] + s[nt][3];
            }
            rs0 += __shfl_xor_sync(0xffffffffu, rs0, 1);
            rs0 += __shfl_xor_sync(0xffffffffu, rs0, 2);
            rs1 += __shfl_xor_sync(0xffffffffu, rs1, 1);
            rs1 += __shfl_xor_sync(0xffffffffu, rs1, 2);
            l0 = l0 * a0 + rs0;  l1 = l1 * a1 + rs1;
            m0 = mn0;            m1 = mn1;
            #pragma unroll
            for (int nt = 0; nt < 8; nt++) {
                oacc[nt][0] *= a0; oacc[nt][1] *= a0;
                oacc[nt][2] *= a1; oacc[nt][3] *= a1;
            }
        }

        // ---- O += P @ V ----
        #pragma unroll
        for (int ks2 = 0; ks2 < 2; ks2++) {
            uint32_t pa[4];
            pa[0] = pack_f16x2(s[2*ks2][0],   s[2*ks2][1]);
            pa[1] = pack_f16x2(s[2*ks2][2],   s[2*ks2][3]);
            pa[2] = pack_f16x2(s[2*ks2+1][0], s[2*ks2+1][1]);
            pa[3] = pack_f16x2(s[2*ks2+1][2], s[2*ks2+1][3]);
            #pragma unroll
            for (int nt = 0; nt < 8; nt++) {
                int dn = nt * 8 + gid;
                int w0 = ks2 * 8 + tig;
                uint32_t vb[2];
                vb[0] = Vs[st][dn * VP2 + w0];
                vb[1] = Vs[st][dn * VP2 + w0 + 4];
                mma_f16(oacc[nt], pa, vb);
            }
        }

        } // per-warp skip

        __syncthreads();
    }

    // epilogue: fp16 straight into final-GEMM A layout
    float inv0 = 1.0f / l0, inv1 = 1.0f / l1;
    __half* ob = o16 + ((size_t)(b * SS + qt * 128 + rb)) * 512 + h * 64;
    #pragma unroll
    for (int nt = 0; nt < 8; nt++) {
        int col = nt * 8 + 2 * tig;
        *(uint32_t*)(ob + (size_t)gid * 512 + col) =
            pack_f16x2(oacc[nt][0] * inv0, oacc[nt][1] * inv0);
        *(uint32_t*)(ob + (size_t)(gid + 8) * 512 + col) =
            pack_f16x2(oacc[nt][2] * inv1, oacc[nt][3] * inv1);
    }
}

// ===========================================================================
// Launch. Input order: query, value, key_in, Wq, Wk, Wv, Wo.
// ===========================================================================
extern "C" void kernel_launch(void* const* d_in, const int* in_sizes, int n_in,
                              void* d_out, int out_size)
{
    const float* query  = (const float*)d_in[0];
    const float* value  = (const float*)d_in[1];
    const float* key_in = (const float*)d_in[2];
    const float* Wq     = (const float*)d_in[3];
    const float* Wk     = (const float*)d_in[4];
    const float* Wv     = (const float*)d_in[5];
    const float* Wo     = (const float*)d_in[6];
    float* out = (float*)d_out;

    float *q, *k, *v;
    __half *a16, *b16, *q16, *k16, *v16;
    cudaGetSymbolAddress((void**)&q,  g_q);
    cudaGetSymbolAddress((void**)&k,  g_k);
    cudaGetSymbolAddress((void**)&v,  g_v);
    cudaGetSymbolAddress((void**)&a16, g_a16);
    cudaGetSymbolAddress((void**)&b16, g_b16);
    cudaGetSymbolAddress((void**)&q16, g_q16);
    cudaGetSymbolAddress((void**)&k16, g_k16);
    cudaGetSymbolAddress((void**)&v16, g_v16);

    const int nA4 = MTOT * GK / 4;
    dim3 ggrid(MTOT / 128, GN / 128);       // (64, 4)
    dim3 wgrid(GK / 32, GN / 32, 4);        // all 4 weights
    dim3 wblk(32, 8);

    // all 4 weight transposes up front
    wt_conv_all<<<wgrid, wblk>>>(Wq, Wk, Wv, Wo, b16);

    // Q = query @ Wq ; K = key_in @ Wk ; V = value @ Wv  (fp32 out for rope/v)
    a_conv_kernel<<<(nA4 + 255) / 256, 256>>>(query, a16, nA4);
    gemm_f16<false><<<ggrid, 256>>>(a16, b16 + 0 * (size_t)GN * GK, q, nullptr);
    a_conv_kernel<<<(nA4 + 255) / 256, 256>>>(key_in, a16, nA4);
    gemm_f16<false><<<ggrid, 256>>>(a16, b16 + 1 * (size_t)GN * GK, k, nullptr);
    a_conv_kernel<<<(nA4 + 255) / 256, 256>>>(value, a16, nA4);
    gemm_f16<false><<<ggrid, 256>>>(a16, b16 + 2 * (size_t)GN * GK, v, nullptr);

    // rope+convert q/k ; transpose+convert v
    const int nrope = BB * SS * HH * 32;
    rope_conv_kernel<<<nrope / 256, 256>>>(q, q16, 0.125f, nrope);
    rope_conv_kernel<<<nrope / 256, 256>>>(k, k16, 1.0f, nrope);
    {
        dim3 vgrid(SS / 32, 2, BB * HH);
        v_conv_kernel<<<vgrid, wblk>>>(v, v16);
    }

    // attention writes fp16 directly into a16 (final-GEMM A layout)
    dim3 agrid(SS / 128, BB * HH);          // (8, 64)
    attn_tc<<<agrid, 256>>>(q16, k16, v16, a16);

    // out = attn_out @ Wo
    gemm_f16<false><<<ggrid, 256>>>(a16, b16 + 3 * (size_t)GN * GK, out, nullptr);
}